// round 15
// baseline (speedup 1.0000x reference)
#include <cuda_runtime.h>
#include <cuda_fp16.h>
#include <cstdint>

#define NB 32
#define NS 512
#define NH 16
#define NDH 64
#define NDM 1024
#define NT 512
#define BH (NB*NH)

// ---------------- global scratch (fp16; A-side operands hi-only) ----------
__device__ __half g_Xqh[NB*NS*NDH];
__device__ __half g_Xkh[NB*NS*NDH];
__device__ __half g_Xvh[NB*NS*NDH];
__device__ __half g_Wqh[NH*NDH*NDH], g_Wql[NH*NDH*NDH];
__device__ __half g_Wkh[NH*NDH*NDH], g_Wkl[NH*NDH*NDH];
__device__ __half g_Wvh[NH*NDH*NDH], g_Wvl[NH*NDH*NDH];
__device__ __half g_Qh [(size_t)BH*NS*NDH];
__device__ __half g_Kth[(size_t)BH*NDH*NS];
__device__ __half g_Ktl[(size_t)BH*NDH*NS];
__device__ __half g_Vth[(size_t)BH*NDH*NS];
__device__ __half g_Vtl[(size_t)BH*NDH*NS];
__device__ __half g_KEh[(size_t)BH*NT*NDH];
__device__ __half g_KEl[(size_t)BH*NT*NDH];
__device__ __half g_VFth[(size_t)BH*NDH*NT];
__device__ __half g_VFtl[(size_t)BH*NDH*NT];
__device__ __half g_Ewh[NT*NS];
__device__ __half g_Fwh[NT*NS];
__device__ __half g_Owh[NDM*NDM], g_Owl[NDM*NDM];
__device__ __half g_HOh[(size_t)BH*NS*NDH];
__device__ float g_ATTN_FB[(size_t)BH*NS*NT];
__device__ float g_MHA_FB [(size_t)NB*NS*NDM];

// ---------------- helpers ----------------
__device__ __forceinline__ uint32_t smem_u32(const void* p) {
    uint32_t a;
    asm("{ .reg .u64 t; cvta.to.shared.u64 t, %1; cvt.u32.u64 %0, t; }" : "=r"(a) : "l"(p));
    return a;
}
__device__ __forceinline__ void mma16816(float c[4],
                                         uint32_t a0, uint32_t a1, uint32_t a2, uint32_t a3,
                                         uint32_t b0, uint32_t b1)
{
    asm volatile(
        "mma.sync.aligned.m16n8k16.row.col.f32.f16.f16.f32 "
        "{%0,%1,%2,%3}, {%4,%5,%6,%7}, {%8,%9}, {%0,%1,%2,%3};"
        : "+f"(c[0]), "+f"(c[1]), "+f"(c[2]), "+f"(c[3])
        : "r"(a0), "r"(a1), "r"(a2), "r"(a3), "r"(b0), "r"(b1));
}
__device__ __forceinline__ void ldmx4(uint32_t& r0, uint32_t& r1, uint32_t& r2, uint32_t& r3,
                                      uint32_t addr)
{
    asm volatile("ldmatrix.sync.aligned.m8n8.x4.shared.b16 {%0,%1,%2,%3}, [%4];"
                 : "=r"(r0), "=r"(r1), "=r"(r2), "=r"(r3) : "r"(addr));
}
__device__ __forceinline__ void cp16(uint32_t saddr, const void* g)
{
    asm volatile("cp.async.cg.shared.global [%0], [%1], 16;" :: "r"(saddr), "l"(g) : "memory");
}
__device__ __forceinline__ void cp_commit() { asm volatile("cp.async.commit_group;" ::: "memory"); }
__device__ __forceinline__ void cp_waitg1() { asm volatile("cp.async.wait_group 1;" ::: "memory"); }
__device__ __forceinline__ void cp_waitg0() { asm volatile("cp.async.wait_group 0;" ::: "memory"); }
__device__ __forceinline__ void cp_wait()
{
    asm volatile("cp.async.commit_group;\n\tcp.async.wait_group 0;" ::: "memory");
}
__device__ __forceinline__ void split2(float x, float y, uint32_t& hi, uint32_t& lo)
{
    __half2 h = __floats2half2_rn(x, y);
    float hx = __low2float(h), hy = __high2float(h);
    __half2 l = __floats2half2_rn(x - hx, y - hy);
    hi = *(uint32_t*)&h;
    lo = *(uint32_t*)&l;
}
__device__ __forceinline__ uint32_t pack_h(float x, float y)
{
    __half2 h = __floats2half2_rn(x, y);
    return *(uint32_t*)&h;
}

// smem geometry: rows padded to 144B
#define A_STRIDE_B 144
#define MI_STEP_B  2304
#define KS_STEP_B  32

// 2-term fp16 chunk (k=64): D += Ah·Bh + Ah·Bl.  Stage (words):
// Ah@0 (128x36=4608) | Bh@4608 (64x36=2304) | Bl@6912 -> 9216 words/stage
#define ST_WORDS 9216
#define MMA_CHUNK2(bu)                                                            \
    { uint32_t aH  = (bu) + (m0w + lrow)*A_STRIDE_B + lsel;                       \
      uint32_t bHo = (bu) + 18432 + (n0w + lrow)*A_STRIDE_B + lsel;               \
      uint32_t bLo = bHo + 9216;                                                  \
      _Pragma("unroll")                                                           \
      for (int ks = 0; ks < 4; ks++) {                                            \
          uint32_t ah[2][4];                                                      \
          _Pragma("unroll")                                                       \
          for (int mi = 0; mi < 2; mi++)                                          \
              ldmx4(ah[mi][0],ah[mi][1],ah[mi][2],ah[mi][3], aH + mi*MI_STEP_B + ks*KS_STEP_B); \
          _Pragma("unroll")                                                       \
          for (int nj2 = 0; nj2 < 2; nj2++) {                                     \
              uint32_t bh[4], bl[4];                                              \
              ldmx4(bh[0],bh[1],bh[2],bh[3], bHo + nj2*MI_STEP_B + ks*KS_STEP_B); \
              ldmx4(bl[0],bl[1],bl[2],bl[3], bLo + nj2*MI_STEP_B + ks*KS_STEP_B); \
              _Pragma("unroll")                                                   \
              for (int jj = 0; jj < 2; jj++) {                                    \
                  int nj = nj2*2 + jj;                                            \
                  _Pragma("unroll")                                               \
                  for (int mi = 0; mi < 2; mi++) {                                \
                      mma16816(acc[mi][nj], ah[mi][0],ah[mi][1],ah[mi][2],ah[mi][3], bh[jj], bh[jj+2]); \
                      mma16816(acc[mi][nj], ah[mi][0],ah[mi][1],ah[mi][2],ah[mi][3], bl[jj], bl[jj+2]); \
                  }                                                               \
              }                                                                   \
          }                                                                       \
      } }

#define LOAD_CHUNK_KV(st, ch)                                                     \
    { uint32_t dst = sb + (st)*ST_WORDS*4;                                        \
      for (int i = tid; i < 1024; i += 256) {                                     \
          int r = i >> 3, c = i & 7;                                              \
          cp16(dst + (r*36 + c*4)*4, gA4h + (size_t)r*64 + (ch)*8 + c);           \
      }                                                                           \
      for (int i = tid; i < 512; i += 256) {                                      \
          int r = i >> 3, c = i & 7;                                              \
          cp16(dst + (4608 + r*36 + c*4)*4, gB4h + (size_t)r*64 + (ch)*8 + c);    \
          cp16(dst + (6912 + r*36 + c*4)*4, gB4l + (size_t)r*64 + (ch)*8 + c);    \
      } }

// ---------------------------------------------------------------------------
// combined split kernels
// ---------------------------------------------------------------------------
#define NX (NB*NS*NDH)
#define NW (NH*NDH*NDH)
__device__ __forceinline__ void split_store4(const float* src, size_t i4,
                                             __half* h, __half* l)
{
    float4 v = ((const float4*)src)[i4];
    uint32_t h0, l0, h1, l1;
    split2(v.x, v.y, h0, l0);
    split2(v.z, v.w, h1, l1);
    *(uint2*)(h + i4*4) = make_uint2(h0, h1);
    *(uint2*)(l + i4*4) = make_uint2(l0, l1);
}
__device__ __forceinline__ void hi_store4(const float* src, size_t i4, __half* h)
{
    float4 v = ((const float4*)src)[i4];
    *(uint2*)(h + i4*4) = make_uint2(pack_h(v.x, v.y), pack_h(v.z, v.w));
}
__global__ void k_split6(const float* __restrict__ xq, const float* __restrict__ xk,
                         const float* __restrict__ xv, const float* __restrict__ wq,
                         const float* __restrict__ wk, const float* __restrict__ wv)
{
    const int NX4 = NX/4, NW4 = NW/4;
    int i = blockIdx.x*256 + threadIdx.x;
    if (i < NX4)                   hi_store4(xq, i, g_Xqh);
    else if (i < 2*NX4)            hi_store4(xk, i - NX4, g_Xkh);
    else if (i < 3*NX4)            hi_store4(xv, i - 2*NX4, g_Xvh);
    else if (i < 3*NX4 + NW4)      split_store4(wq, i - 3*NX4, g_Wqh, g_Wql);
    else if (i < 3*NX4 + 2*NW4)    split_store4(wk, i - 3*NX4 - NW4, g_Wkh, g_Wkl);
    else if (i < 3*NX4 + 3*NW4)    split_store4(wv, i - 3*NX4 - 2*NW4, g_Wvh, g_Wvl);
}
__global__ void k_split3(const float* __restrict__ ew, const float* __restrict__ fw,
                         const float* __restrict__ ow)
{
    const int NE4 = (NT*NS)/4, NO4 = (NDM*NDM)/4;
    int i = blockIdx.x*256 + threadIdx.x;
    if (i < NE4)                   hi_store4(ew, i, g_Ewh);
    else if (i < 2*NE4)            hi_store4(fw, i - NE4, g_Fwh);
    else if (i < 2*NE4 + NO4)      split_store4(ow, i - 2*NE4, g_Owh, g_Owl);
}

// ---------------------------------------------------------------------------
// k_qkv_mma (unchanged from r14)
// ---------------------------------------------------------------------------
__global__ void __launch_bounds__(256, 3) k_qkv_mma(const float* __restrict__ bq,
                                                    const float* __restrict__ bk,
                                                    const float* __restrict__ bv)
{
    extern __shared__ uint32_t sm32[];
    int tid = threadIdx.x, wid = tid >> 5, lane = tid & 31;
    int g = lane >> 2, t4 = lane & 3;
    int m0w = (wid & 3)*32, n0w = (wid >> 2)*32;
    int bh = blockIdx.x, b = bh >> 4, h = bh & 15;
    int s0 = blockIdx.y << 7, z = blockIdx.z;

    uint32_t sb = smem_u32(sm32);
    uint32_t lrow = lane & 15, lsel = (lane >> 4) << 4;

    const uint4 *gA4h, *gB4h, *gB4l;
    const float* bias;
    if (z == 0)      { gA4h = (const uint4*)(g_Xqh + ((size_t)b*NS + s0)*NDH);
                       gB4h = (const uint4*)(g_Wqh + h*4096);
                       gB4l = (const uint4*)(g_Wql + h*4096); bias = bq + h*64; }
    else if (z == 1) { gA4h = (const uint4*)(g_Xkh + ((size_t)b*NS + s0)*NDH);
                       gB4h = (const uint4*)(g_Wkh + h*4096);
                       gB4l = (const uint4*)(g_Wkl + h*4096); bias = bk + h*64; }
    else             { gA4h = (const uint4*)(g_Xvh + ((size_t)b*NS + s0)*NDH);
                       gB4h = (const uint4*)(g_Wvh + h*4096);
                       gB4l = (const uint4*)(g_Wvl + h*4096); bias = bv + h*64; }

    float acc[2][4][4];
#pragma unroll
    for (int mi = 0; mi < 2; mi++)
#pragma unroll
        for (int nj = 0; nj < 4; nj++)
#pragma unroll
            for (int q = 0; q < 4; q++) acc[mi][nj][q] = 0.f;

    for (int i = tid; i < 1024; i += 256) {
        int r = i >> 3, c = i & 7;
        cp16(sb + (r*36 + c*4)*4, gA4h + (size_t)r*8 + c);
    }
    for (int i = tid; i < 512; i += 256) {
        int r = i >> 3, c = i & 7;
        cp16(sb + (4608 + r*36 + c*4)*4, gB4h + (size_t)r*8 + c);
        cp16(sb + (6912 + r*36 + c*4)*4, gB4l + (size_t)r*8 + c);
    }
    cp_wait();
    __syncthreads();
    MMA_CHUNK2(sb);

    if (z == 0) {
        size_t base = (size_t)bh*NS*NDH;
#pragma unroll
        for (int mi = 0; mi < 2; mi++) {
            int m = m0w + mi*16 + g;
#pragma unroll
            for (int nj = 0; nj < 4; nj++) {
                int n = n0w + nj*8 + t4*2;
                float b0 = bias[n], b1 = bias[n + 1];
                size_t i0 = base + (size_t)(s0 + m)*NDH + n;
                *(uint32_t*)(g_Qh + i0) = pack_h(acc[mi][nj][0] + b0, acc[mi][nj][1] + b1);
                size_t i1 = base + (size_t)(s0 + m + 8)*NDH + n;
                *(uint32_t*)(g_Qh + i1) = pack_h(acc[mi][nj][2] + b0, acc[mi][nj][3] + b1);
            }
        }
    } else {
        __syncthreads();
        float* Sg = (float*)sm32;
#pragma unroll
        for (int mi = 0; mi < 2; mi++) {
            int m = m0w + mi*16 + g;
#pragma unroll
            for (int nj = 0; nj < 4; nj++) {
                int n = n0w + nj*8 + t4*2;
                float b0 = bias[n], b1 = bias[n + 1];
                Sg[n*129 + m]         = acc[mi][nj][0] + b0;
                Sg[(n+1)*129 + m]     = acc[mi][nj][1] + b1;
                Sg[n*129 + m + 8]     = acc[mi][nj][2] + b0;
                Sg[(n+1)*129 + m + 8] = acc[mi][nj][3] + b1;
            }
        }
        __syncthreads();
        __half* dh = (z == 1 ? g_Kth : g_Vth);
        __half* dl = (z == 1 ? g_Ktl : g_Vtl);
        size_t base = (size_t)bh*NDH*NS;
        for (int i = tid; i < 4096; i += 256) {
            int d = i >> 6, mm = (i & 63)*2;
            uint32_t hi, lo;
            split2(Sg[d*129 + mm], Sg[d*129 + mm + 1], hi, lo);
            size_t idx = base + (size_t)d*NS + s0 + mm;
            *(uint32_t*)(dh + idx) = hi;
            *(uint32_t*)(dl + idx) = lo;
        }
    }
}

// ---------------------------------------------------------------------------
// k_kevf_mma: merged ke/vf (blockIdx.z). 8 chunks double-buffered, occ 3.
// ---------------------------------------------------------------------------
__global__ void __launch_bounds__(256, 3) k_kevf_mma(const float* __restrict__ Eb,
                                                     const float* __restrict__ Fb)
{
    extern __shared__ uint32_t sm32[];
    int tid = threadIdx.x, wid = tid >> 5, lane = tid & 31;
    int g = lane >> 2, t4 = lane & 3;
    int m0w = (wid & 3)*32, n0w = (wid >> 2)*32;
    int bh = blockIdx.x, t0 = blockIdx.y << 7, z = blockIdx.z;

    uint32_t sb = smem_u32(sm32);
    uint32_t lrow = lane & 15, lsel = (lane >> 4) << 4;

    float acc[2][4][4];
#pragma unroll
    for (int mi = 0; mi < 2; mi++)
#pragma unroll
        for (int nj = 0; nj < 4; nj++)
#pragma unroll
            for (int q = 0; q < 4; q++) acc[mi][nj][q] = 0.f;

    const uint4* gA4h = (const uint4*)((z == 0 ? g_Ewh : g_Fwh) + (size_t)t0*NS);
    const uint4* gB4h = (const uint4*)((z == 0 ? g_Kth : g_Vth) + (size_t)bh*NDH*NS);
    const uint4* gB4l = (const uint4*)((z == 0 ? g_Ktl : g_Vtl) + (size_t)bh*NDH*NS);

    LOAD_CHUNK_KV(0, 0);
    cp_commit();
    for (int ch = 0; ch < 8; ch++) {
        if (ch < 7) {
            LOAD_CHUNK_KV((ch+1)&1, ch+1);
            cp_commit();
            cp_waitg1();
        } else cp_waitg0();
        __syncthreads();
        MMA_CHUNK2(sb + (ch&1)*ST_WORDS*4);
        __syncthreads();
    }

    if (z == 0) {
        size_t base = (size_t)bh*NT*NDH;
#pragma unroll
        for (int mi = 0; mi < 2; mi++) {
            int m = m0w + mi*16 + g;
            float e0 = Eb[t0 + m];
            float e1 = Eb[t0 + m + 8];
#pragma unroll
            for (int nj = 0; nj < 4; nj++) {
                int n = n0w + nj*8 + t4*2;
                uint32_t hi, lo;
                size_t i0 = base + (size_t)(t0 + m)*NDH + n;
                split2(acc[mi][nj][0] + e0, acc[mi][nj][1] + e0, hi, lo);
                *(uint32_t*)(g_KEh + i0) = hi;  *(uint32_t*)(g_KEl + i0) = lo;
                size_t i1 = base + (size_t)(t0 + m + 8)*NDH + n;
                split2(acc[mi][nj][2] + e1, acc[mi][nj][3] + e1, hi, lo);
                *(uint32_t*)(g_KEh + i1) = hi;  *(uint32_t*)(g_KEl + i1) = lo;
            }
        }
    } else {
        float* Sg = (float*)sm32;
#pragma unroll
        for (int mi = 0; mi < 2; mi++) {
            int m = m0w + mi*16 + g;
            float f0 = Fb[t0 + m];
            float f1 = Fb[t0 + m + 8];
#pragma unroll
            for (int nj = 0; nj < 4; nj++) {
                int n = n0w + nj*8 + t4*2;
                Sg[n*129 + m]         = acc[mi][nj][0] + f0;
                Sg[(n+1)*129 + m]     = acc[mi][nj][1] + f0;
                Sg[n*129 + m + 8]     = acc[mi][nj][2] + f1;
                Sg[(n+1)*129 + m + 8] = acc[mi][nj][3] + f1;
            }
        }
        __syncthreads();
        size_t base = (size_t)bh*NDH*NT;
        for (int i = tid; i < 4096; i += 256) {
            int d = i >> 6, mm = (i & 63)*2;
            uint32_t hi, lo;
            split2(Sg[d*129 + mm], Sg[d*129 + mm + 1], hi, lo);
            size_t idx = base + (size_t)d*NT + t0 + mm;
            *(uint32_t*)(g_VFth + idx) = hi;
            *(uint32_t*)(g_VFtl + idx) = lo;
        }
    }
}

// ---------------------------------------------------------------------------
// k_attn_fused: QK pipelined over 4x128-row KE chunks; softmax; attn; PV.
// smem (words): KE stage0@0 (9216: hi 4608|lo 4608) | stage1@9216 | Qh@18432 (1152)
//               | redm@20736 | reds@20992 -> 21248 w = 84992 B, occ 2.
// Warp wid's S cols: ch*128 + wid*16 + jj*8 + 2*t4 (nj = ch*2 + jj).
// ---------------------------------------------------------------------------
#define LOAD_KE(st, ch)                                                           \
    { uint32_t dst = sb + (st)*ST_WORDS*4;                                        \
      for (int i = tid; i < 1024; i += 256) {                                     \
          int r = i >> 3, c = i & 7;                                              \
          cp16(dst + (r*36 + c*4)*4,        gKE4h + (size_t)((ch)*128 + r)*8 + c);\
          cp16(dst + (4608 + r*36 + c*4)*4, gKE4l + (size_t)((ch)*128 + r)*8 + c);\
      } }

#define LOAD_VF(dh, hf, stw)                                                      \
    { for (int i = tid; i < 1024; i += 256) {                                     \
          int r = i >> 5, c = i & 31;                                             \
          cp16(sb + ((stw) + r*132 + c*4)*4,        gVF4h + (size_t)((dh)*32 + r)*64 + (hf)*32 + c); \
          cp16(sb + ((stw) + 4224 + r*132 + c*4)*4, gVF4l + (size_t)((dh)*32 + r)*64 + (hf)*32 + c); \
      } cp_commit(); }

// PV for half hf: P k-window ke=hf*2+ks2 covers t_local = ks2*128 + wid*16
#define PV_COMPUTE(hf, stw)                                                       \
    { uint32_t bH = sb + (stw)*4 + lrow*528 + lsel;                               \
      uint32_t bL = bH + 16896;                                                   \
      _Pragma("unroll")                                                           \
      for (int dt = 0; dt < 2; dt++)                                              \
      _Pragma("unroll")                                                           \
      for (int ks2 = 0; ks2 < 2; ks2++) {                                         \
          int ke = (hf)*2 + ks2;                                                  \
          uint32_t off = dt*8448 + ks2*256 + wid*32;                              \
          uint32_t bhv[4], blv[4];                                                \
          ldmx4(bhv[0],bhv[1],bhv[2],bhv[3], bH + off);                           \
          ldmx4(blv[0],blv[1],blv[2],blv[3], bL + off);                           \
          _Pragma("unroll")                                                       \
          for (int jj = 0; jj < 2; jj++) {                                        \
              int nd = dt*2 + jj;                                                 \
              _Pragma("unroll")                                                   \
              for (int mi = 0; mi < 2; mi++) {                                    \
                  mma16816(acc_o[mi][nd], pah[ke][mi][0],pah[ke][mi][1],pah[ke][mi][2],pah[ke][mi][3], bhv[jj], bhv[jj+2]); \
                  mma16816(acc_o[mi][nd], pah[ke][mi][0],pah[ke][mi][1],pah[ke][mi][2],pah[ke][mi][3], blv[jj], blv[jj+2]); \
              }                                                                   \
          }                                                                       \
      } }

__global__ void __launch_bounds__(256, 2) k_attn_fused(float* __restrict__ attn_out)
{
    extern __shared__ uint32_t sm32[];
    float* sredm = (float*)(sm32 + 20736);
    float* sreds = (float*)(sm32 + 20992);
    int tid = threadIdx.x, wid = tid >> 5, lane = tid & 31;
    int g = lane >> 2, t4 = lane & 3;
    int s0 = blockIdx.x << 5, bh = blockIdx.y;

    uint32_t sb = smem_u32(sm32);
    uint32_t lrow = lane & 15, lsel = (lane >> 4) << 4;
    uint32_t aoffH = sb + 73728 + lrow*A_STRIDE_B + lsel;   // Q @ word 18432

    const uint4* gVF4h = (const uint4*)(g_VFth + (size_t)bh*NDH*NT);
    const uint4* gVF4l = (const uint4*)(g_VFtl + (size_t)bh*NDH*NT);
    const uint4* gKE4h = (const uint4*)(g_KEh + (size_t)bh*NT*NDH);
    const uint4* gKE4l = (const uint4*)(g_KEl + (size_t)bh*NT*NDH);
    const uint4* gQ4h  = (const uint4*)(g_Qh + ((size_t)bh*NS + s0)*NDH);

    // Q + KE chunk 0 in group 0
    {
        int r = tid >> 3, c = tid & 7;
        cp16(sb + (18432 + r*36 + c*4)*4, gQ4h + (size_t)r*8 + c);
    }
    LOAD_KE(0, 0);
    cp_commit();

    float acc[2][8][4];
#pragma unroll
    for (int mi = 0; mi < 2; mi++)
#pragma unroll
        for (int nj = 0; nj < 8; nj++)
#pragma unroll
            for (int q = 0; q < 4; q++) acc[mi][nj][q] = 0.f;

    for (int ch = 0; ch < 4; ch++) {
        if (ch < 3) {
            LOAD_KE((ch+1)&1, ch+1);
            cp_commit();
            cp_waitg1();
        } else cp_waitg0();
        __syncthreads();
        uint32_t bst = sb + (ch&1)*ST_WORDS*4;
        uint32_t boffH = bst + (wid*16 + lrow)*A_STRIDE_B + lsel;
        uint32_t boffL = boffH + 18432;
#pragma unroll
        for (int ks = 0; ks < 4; ks++) {
            uint32_t ah[2][4];
#pragma unroll
            for (int mi = 0; mi < 2; mi++)
                ldmx4(ah[mi][0],ah[mi][1],ah[mi][2],ah[mi][3], aoffH + mi*MI_STEP_B + ks*KS_STEP_B);
            uint32_t bhp[4], blp[4];
            ldmx4(bhp[0],bhp[1],bhp[2],bhp[3], boffH + ks*KS_STEP_B);
            ldmx4(blp[0],blp[1],blp[2],blp[3], boffL + ks*KS_STEP_B);
#pragma unroll
            for (int jj = 0; jj < 2; jj++) {
                int nj = ch*2 + jj;
#pragma unroll
                for (int mi = 0; mi < 2; mi++) {
                    mma16816(acc[mi][nj], ah[mi][0],ah[mi][1],ah[mi][2],ah[mi][3], bhp[jj], bhp[jj+2]);
                    mma16816(acc[mi][nj], ah[mi][0],ah[mi][1],ah[mi][2],ah[mi][3], blp[jj], blp[jj+2]);
                }
            }
        }
        __syncthreads();
    }

    // prefetch dh=0 VF during softmax
    LOAD_VF(0, 0, 0);
    LOAD_VF(0, 1, 8448);

    // ---- softmax ----
    float lm[2][2];
#pragma unroll
    for (int mi = 0; mi < 2; mi++) { lm[mi][0] = -1e30f; lm[mi][1] = -1e30f; }
#pragma unroll
    for (int mi = 0; mi < 2; mi++)
#pragma unroll
        for (int nj = 0; nj < 8; nj++) {
#pragma unroll
            for (int q = 0; q < 4; q++) acc[mi][nj][q] *= 0.125f;
            lm[mi][0] = fmaxf(lm[mi][0], fmaxf(acc[mi][nj][0], acc[mi][nj][1]));
            lm[mi][1] = fmaxf(lm[mi][1], fmaxf(acc[mi][nj][2], acc[mi][nj][3]));
        }
#pragma unroll
    for (int mi = 0; mi < 2; mi++)
#pragma unroll
        for (int hh = 0; hh < 2; hh++) {
            lm[mi][hh] = fmaxf(lm[mi][hh], __shfl_xor_sync(0xffffffffu, lm[mi][hh], 1));
            lm[mi][hh] = fmaxf(lm[mi][hh], __shfl_xor_sync(0xffffffffu, lm[mi][hh], 2));
        }
    if (t4 == 0) {
#pragma unroll
        for (int mi = 0; mi < 2; mi++) {
            sredm[wid*32 + mi*16 + g]     = lm[mi][0];
            sredm[wid*32 + mi*16 + g + 8] = lm[mi][1];
        }
    }
    __syncthreads();
    float rowm[2][2];
#pragma unroll
    for (int mi = 0; mi < 2; mi++)
#pragma unroll
        for (int hh = 0; hh < 2; hh++) {
            int row = mi*16 + g + hh*8;
            float m = sredm[row];
#pragma unroll
            for (int w = 1; w < 8; w++) m = fmaxf(m, sredm[w*32 + row]);
            rowm[mi][hh] = m;
        }
    float ls[2][2] = {{0.f,0.f},{0.f,0.f}};
#pragma unroll
    for (int mi = 0; mi < 2; mi++)
#pragma unroll
        for (int nj = 0; nj < 8; nj++) {
            acc[mi][nj][0] = __expf(acc[mi][nj][0] - rowm[mi][0]);
            acc[mi][nj][1] = __expf(acc[mi][nj][1] - rowm[mi][0]);
            acc[mi][nj][2] = __expf(acc[mi][nj][2] - rowm[mi][1]);
            acc[mi][nj][3] = __expf(acc[mi][nj][3] - rowm[mi][1]);
            ls[mi][0] += acc[mi][nj][0] + acc[mi][nj][1];
            ls[mi][1] += acc[mi][nj][2] + acc[mi][nj][3];
        }
#pragma unroll
    for (int mi = 0; mi < 2; mi++)
#pragma unroll
        for (int hh = 0; hh < 2; hh++) {
            ls[mi][hh] += __shfl_xor_sync(0xffffffffu, ls[mi][hh], 1);
            ls[mi][hh] += __shfl_xor_sync(0xffffffffu, ls[mi][hh], 2);
        }
    if (t4 == 0) {
#pragma unroll
        for (int mi = 0; mi < 2; mi++) {
            sreds[wid*32 + mi*16 + g]     = ls[mi][0];
            sreds[wid*32 + mi*16 + g + 8] = ls[mi][1];
        }
    }
    __syncthreads();
    float inv[2][2];
#pragma unroll
    for (int mi = 0; mi < 2; mi++)
#pragma unroll
        for (int hh = 0; hh < 2; hh++) {
            int row = mi*16 + g + hh*8;
            float s = 0.f;
#pragma unroll
            for (int w = 0; w < 8; w++) s += sreds[w*32 + row];
            inv[mi][hh] = 1.f / s;
        }

    // normalize, write attn (col = ch*128 + wid*16 + jj*8 + 2*t4), P frags
    uint32_t pah[4][2][4];
#pragma unroll
    for (int ch = 0; ch < 4; ch++)
#pragma unroll
        for (int mi = 0; mi < 2; mi++) {
            int nj0 = ch*2, nj1 = ch*2 + 1;
            size_t r0 = ((size_t)bh*NS + s0 + mi*16 + g)*NT;
            size_t r1 = r0 + 8*NT;
            int c0 = ch*128 + wid*16 + 2*t4;
            acc[mi][nj0][0] *= inv[mi][0];  acc[mi][nj0][1] *= inv[mi][0];
            acc[mi][nj0][2] *= inv[mi][1];  acc[mi][nj0][3] *= inv[mi][1];
            acc[mi][nj1][0] *= inv[mi][0];  acc[mi][nj1][1] *= inv[mi][0];
            acc[mi][nj1][2] *= inv[mi][1];  acc[mi][nj1][3] *= inv[mi][1];
            __stcs((float2*)(attn_out + r0 + c0),     make_float2(acc[mi][nj0][0], acc[mi][nj0][1]));
            __stcs((float2*)(attn_out + r1 + c0),     make_float2(acc[mi][nj0][2], acc[mi][nj0][3]));
            __stcs((float2*)(attn_out + r0 + c0 + 8), make_float2(acc[mi][nj1][0], acc[mi][nj1][1]));
            __stcs((float2*)(attn_out + r1 + c0 + 8), make_float2(acc[mi][nj1][2], acc[mi][nj1][3]));
            pah[ch][mi][0] = pack_h(acc[mi][nj0][0], acc[mi][nj0][1]);
            pah[ch][mi][1] = pack_h(acc[mi][nj0][2], acc[mi][nj0][3]);
            pah[ch][mi][2] = pack_h(acc[mi][nj1][0], acc[mi][nj1][1]);
            pah[ch][mi][3] = pack_h(acc[mi][nj1][2], acc[mi][nj1][3]);
        }

    for (int dh = 0; dh < 2; dh++) {
        if (dh == 1) {
            LOAD_VF(1, 0, 0);
            LOAD_VF(1, 1, 8448);
        }
        float acc_o[2][4][4];
#pragma unroll
        for (int mi = 0; mi < 2; mi++)
#pragma unroll
            for (int nd = 0; nd < 4; nd++)
#pragma unroll
                for (int q = 0; q < 4; q++) acc_o[mi][nd][q] = 0.f;

        cp_waitg1();
        __syncthreads();
        PV_COMPUTE(0, 0);
        cp_waitg0();
        __syncthreads();
        PV_COMPUTE(1, 8448);

        __syncthreads();
        float* Ob = (float*)sm32;
#pragma unroll
        for (int mi = 0; mi < 2; mi++)
#pragma unroll
            for (int nd = 0; nd < 4; nd++) {
                int m = mi*16 + g, n = nd*8 + 2*t4;
                Ob[wid*1056 + m*33 + n]       = acc_o[mi][nd][0];
                Ob[wid*1056 + m*33 + n + 1]   = acc_o[mi][nd][1];
                Ob[wid*1056 + (m+8)*33 + n]   = acc_o[mi][nd][2];
                Ob[wid*1056 + (m+8)*33 + n+1] = acc_o[mi][nd][3];
            }
        __syncthreads();
        {
            int s = tid >> 3, dg = (tid & 7)*4;
            float o[4] = {0.f, 0.f, 0.f, 0.f};
#pragma unroll
            for (int w = 0; w < 8; w++)
#pragma unroll
                for (int j = 0; j < 4; j++) o[j] += Ob[w*1056 + s*33 + dg + j];
            size_t base = ((size_t)bh*NS + s0 + s)*NDH + dh*32 + dg;
            *(uint32_t*)(g_HOh + base)     = pack_h(o[0], o[1]);
            *(uint32_t*)(g_HOh + base + 2) = pack_h(o[2], o[3]);
        }
        __syncthreads();
    }
}

// ---------------------------------------------------------------------------
// k_out_mma (unchanged from r14)
// ---------------------------------------------------------------------------
__global__ void __launch_bounds__(256, 2) k_out_mma(const float* __restrict__ Ob,
                                                    float* __restrict__ out)
{
    extern __shared__ uint32_t sm32[];
    int tid = threadIdx.x, wid = tid >> 5, lane = tid & 31;
    int g = lane >> 2, t4 = lane & 3;
    int m0w = (wid & 3)*32, n0w = (wid >> 2)*64;
    int n0 = blockIdx.x << 7;
    int m0 = blockIdx.y << 7;
    int b  = blockIdx.y >> 2;
    int sbase = (blockIdx.y & 3) << 7;

    uint32_t sb = smem_u32(sm32);
    uint32_t lrow = lane & 15, lsel = (lane >> 4) << 4;

    float acc[2][8][4];
#pragma unroll
    for (int mi = 0; mi < 2; mi++)
#pragma unroll
        for (int nj = 0; nj < 8; nj++)
#pragma unroll
            for (int q = 0; q < 4; q++) acc[mi][nj][q] = 0.f;

    const uint4* gB4h = (const uint4*)(g_Owh + (size_t)n0*NDM);
    const uint4* gB4l = (const uint4*)(g_Owl + (size_t)n0*NDM);

#define LOAD_CHUNK_OUT(st, kc)                                                    \
    { uint32_t dst = sb + (st)*55296;                                             \
      const uint4* gA4h = (const uint4*)(g_HOh + ((size_t)(b*NH + (kc))*NS + sbase)*NDH); \
      for (int i = tid; i < 1024; i += 256) {                                     \
          int r = i >> 3, c = i & 7;                                              \
          cp16(dst + (r*36 + c*4)*4, gA4h + (size_t)r*8 + c);                     \
      }                                                                           \
      for (int i = tid; i < 1024; i += 256) {                                     \
          int r = i >> 3, c = i & 7;                                              \
          cp16(dst + (4608 + r*36 + c*4)*4, gB4h + (size_t)r*128 + (kc)*8 + c);   \
          cp16(dst + (9216 + r*36 + c*4)*4, gB4l + (size_t)r*128 + (kc)*8 + c);   \
      } }

    LOAD_CHUNK_OUT(0, 0);
    cp_commit();
    for (int kc = 0; kc < 16; kc++) {
        if (kc < 15) {
            LOAD_CHUNK_OUT((kc+1)&1, kc+1);
            cp_commit();
            cp_waitg1();
        } else cp_waitg0();
        __syncthreads();
        uint32_t bu = sb + (kc&1)*55296;
        uint32_t aH  = bu + (m0w + lrow)*A_STRIDE_B + lsel;
        uint32_t bHo = bu + 18432 + (n0w + lrow)*A_STRIDE_B + lsel;
        uint32_t bLo = bHo + 18432;
#pragma unroll
        for (int ks = 0; ks < 4; ks++) {
            uint32_t ah[2][4];
#pragma unroll
            for (int mi = 0; mi < 2; mi++)
                ldmx4(ah[mi][0],ah[mi][1],ah[mi][2],ah[mi][3], aH + mi*MI_STEP_B + ks*KS_STEP_B);
#pragma unroll
            for (int nj2 = 0; nj2 < 4; nj2++) {
                uint32_t bh[4], bl[4];
                ldmx4(bh[0],bh[1],bh[2],bh[3], bHo + nj2*MI_STEP_B + ks*KS_STEP_B);
                ldmx4(bl[0],bl[1],bl[2],bl[3], bLo + nj2*MI_STEP_B + ks*KS_STEP_B);
#pragma unroll
                for (int jj = 0; jj < 2; jj++) {
                    int nj = nj2*2 + jj;
#pragma unroll
                    for (int mi = 0; mi < 2; mi++) {
                        mma16816(acc[mi][nj], ah[mi][0],ah[mi][1],ah[mi][2],ah[mi][3], bh[jj], bh[jj+2]);
                        mma16816(acc[mi][nj], ah[mi][0],ah[mi][1],ah[mi][2],ah[mi][3], bl[jj], bl[jj+2]);
                    }
                }
            }
        }
        __syncthreads();
    }

    float* Sg = (float*)sm32;
#pragma unroll
    for (int mi = 0; mi < 2; mi++) {
        int m = m0w + mi*16 + g;
#pragma unroll
        for (int nj = 0; nj < 8; nj++) {
            int n = n0w + nj*8 + t4*2;
            float o0 = Ob[n0 + n];
            float o1 = Ob[n0 + n + 1];
            Sg[m*129 + n]         = acc[mi][nj][0] + o0;
            Sg[m*129 + n + 1]     = acc[mi][nj][1] + o1;
            Sg[(m+8)*129 + n]     = acc[mi][nj][2] + o0;
            Sg[(m+8)*129 + n + 1] = acc[mi][nj][3] + o1;
        }
    }
    __syncthreads();
    for (int i = tid; i < 4096; i += 256) {
        int r = i >> 5, c4 = (i & 31)*4;
        float4 v = make_float4(Sg[r*129 + c4], Sg[r*129 + c4 + 1],
                               Sg[r*129 + c4 + 2], Sg[r*129 + c4 + 3]);
        __stcs((float4*)(out + (size_t)(m0 + r)*NDM + n0 + c4), v);
    }
}

// ---------------------------------------------------------------------------
extern "C" void kernel_launch(void* const* d_in, const int* in_sizes, int n_in,
                              void* d_out, int out_size)
{
    const float* query = (const float*)d_in[0];
    const float* key   = (const float*)d_in[1];
    const float* value = (const float*)d_in[2];
    const float* Wq    = (const float*)d_in[3];
    const float* bq    = (const float*)d_in[4];
    const float* Wk    = (const float*)d_in[5];
    const float* bk    = (const float*)d_in[6];
    const float* Wv    = (const float*)d_in[7];
    const float* bv    = (const float*)d_in[8];
    const float* E_w   = (const float*)d_in[9];
    const float* E_b   = (const float*)d_in[10];
    const float* F_w   = (const float*)d_in[11];
    const float* F_b   = (const float*)d_in[12];
    const float* out_w = (const float*)d_in[13];
    const float* out_b = (const float*)d_in[14];

    const long long mha_elems  = (long long)NB*NS*NDM;
    const long long attn_elems = (long long)BH*NS*NT;

    float* outp = (float*)d_out;
    float* mha_ptr;
    float* attn_ptr;
    if ((long long)out_size >= mha_elems + attn_elems) {
        mha_ptr  = outp;
        attn_ptr = outp + mha_elems;
    } else if ((long long)out_size == attn_elems) {
        attn_ptr = outp;
        cudaGetSymbolAddress((void**)&mha_ptr, g_MHA_FB);
    } else {
        mha_ptr = outp;
        cudaGetSymbolAddress((void**)&attn_ptr, g_ATTN_FB);
    }

    cudaFuncSetAttribute(k_qkv_mma,    cudaFuncAttributeMaxDynamicSharedMemorySize, 36864);
    cudaFuncSetAttribute(k_kevf_mma,   cudaFuncAttributeMaxDynamicSharedMemorySize, 73728);
    cudaFuncSetAttribute(k_out_mma,    cudaFuncAttributeMaxDynamicSharedMemorySize, 110592);
    cudaFuncSetAttribute(k_attn_fused, cudaFuncAttributeMaxDynamicSharedMemorySize, 84992);

    k_split6<<<((3*NX + 3*NW)/4 + 255)/256, 256>>>(query, key, value, Wq, Wk, Wv);
    k_split3<<<((2*NT*NS + NDM*NDM)/4 + 255)/256, 256>>>(E_w, F_w, out_w);
    k_qkv_mma<<<dim3(BH, 4, 3), 256, 36864>>>(bq, bk, bv);
    k_kevf_mma<<<dim3(BH, 4, 2), 256, 73728>>>(E_b, F_b);
    k_attn_fused<<<dim3(16, BH), 256, 84992>>>(attn_ptr);
    k_out_mma<<<dim3(NDM/128, (NB*NS)/128), 256, 110592>>>(out_b, mha_ptr);
}

// round 16
// speedup vs baseline: 1.0185x; 1.0185x over previous
#include <cuda_runtime.h>
#include <cuda_fp16.h>
#include <cstdint>

#define NB 32
#define NS 512
#define NH 16
#define NDH 64
#define NDM 1024
#define NT 512
#define BH (NB*NH)

// ---------------- global scratch (fp16; A-side operands hi-only) ----------
__device__ __half g_Xqh[NB*NS*NDH];
__device__ __half g_Xkh[NB*NS*NDH];
__device__ __half g_Xvh[NB*NS*NDH];
__device__ __half g_Wqh[NH*NDH*NDH], g_Wql[NH*NDH*NDH];
__device__ __half g_Wkh[NH*NDH*NDH], g_Wkl[NH*NDH*NDH];
__device__ __half g_Wvh[NH*NDH*NDH], g_Wvl[NH*NDH*NDH];
__device__ __half g_Qh [(size_t)BH*NS*NDH];
__device__ __half g_Kth[(size_t)BH*NDH*NS];
__device__ __half g_Ktl[(size_t)BH*NDH*NS];
__device__ __half g_Vth[(size_t)BH*NDH*NS];
__device__ __half g_Vtl[(size_t)BH*NDH*NS];
__device__ __half g_KEh[(size_t)BH*NT*NDH];
__device__ __half g_KEl[(size_t)BH*NT*NDH];
__device__ __half g_VFth[(size_t)BH*NDH*NT];
__device__ __half g_VFtl[(size_t)BH*NDH*NT];
__device__ __half g_Ewh[NT*NS];
__device__ __half g_Fwh[NT*NS];
__device__ __half g_Owh[NDM*NDM], g_Owl[NDM*NDM];
__device__ __half g_HOh[(size_t)BH*NS*NDH];
__device__ float g_ATTN_FB[(size_t)BH*NS*NT];
__device__ float g_MHA_FB [(size_t)NB*NS*NDM];

// ---------------- helpers ----------------
__device__ __forceinline__ uint32_t smem_u32(const void* p) {
    uint32_t a;
    asm("{ .reg .u64 t; cvta.to.shared.u64 t, %1; cvt.u32.u64 %0, t; }" : "=r"(a) : "l"(p));
    return a;
}
__device__ __forceinline__ void mma16816(float c[4],
                                         uint32_t a0, uint32_t a1, uint32_t a2, uint32_t a3,
                                         uint32_t b0, uint32_t b1)
{
    asm volatile(
        "mma.sync.aligned.m16n8k16.row.col.f32.f16.f16.f32 "
        "{%0,%1,%2,%3}, {%4,%5,%6,%7}, {%8,%9}, {%0,%1,%2,%3};"
        : "+f"(c[0]), "+f"(c[1]), "+f"(c[2]), "+f"(c[3])
        : "r"(a0), "r"(a1), "r"(a2), "r"(a3), "r"(b0), "r"(b1));
}
__device__ __forceinline__ void ldmx4(uint32_t& r0, uint32_t& r1, uint32_t& r2, uint32_t& r3,
                                      uint32_t addr)
{
    asm volatile("ldmatrix.sync.aligned.m8n8.x4.shared.b16 {%0,%1,%2,%3}, [%4];"
                 : "=r"(r0), "=r"(r1), "=r"(r2), "=r"(r3) : "r"(addr));
}
__device__ __forceinline__ void cp16(uint32_t saddr, const void* g)
{
    asm volatile("cp.async.cg.shared.global [%0], [%1], 16;" :: "r"(saddr), "l"(g) : "memory");
}
__device__ __forceinline__ void cp_commit() { asm volatile("cp.async.commit_group;" ::: "memory"); }
__device__ __forceinline__ void cp_waitg1() { asm volatile("cp.async.wait_group 1;" ::: "memory"); }
__device__ __forceinline__ void cp_waitg0() { asm volatile("cp.async.wait_group 0;" ::: "memory"); }
__device__ __forceinline__ void cp_wait()
{
    asm volatile("cp.async.commit_group;\n\tcp.async.wait_group 0;" ::: "memory");
}
__device__ __forceinline__ void split2(float x, float y, uint32_t& hi, uint32_t& lo)
{
    __half2 h = __floats2half2_rn(x, y);
    float hx = __low2float(h), hy = __high2float(h);
    __half2 l = __floats2half2_rn(x - hx, y - hy);
    hi = *(uint32_t*)&h;
    lo = *(uint32_t*)&l;
}
__device__ __forceinline__ uint32_t pack_h(float x, float y)
{
    __half2 h = __floats2half2_rn(x, y);
    return *(uint32_t*)&h;
}

// smem geometry: rows padded to 144B
#define A_STRIDE_B 144
#define MI_STEP_B  2304
#define KS_STEP_B  32

// 2-term fp16 chunk (k=64): D += Ah·Bh + Ah·Bl.  Stage (words):
// Ah@0 (128x36=4608) | Bh@4608 (64x36=2304) | Bl@6912 -> 9216 words/stage
#define ST_WORDS 9216
#define MMA_CHUNK2(bu)                                                            \
    { uint32_t aH  = (bu) + (m0w + lrow)*A_STRIDE_B + lsel;                       \
      uint32_t bHo = (bu) + 18432 + (n0w + lrow)*A_STRIDE_B + lsel;               \
      uint32_t bLo = bHo + 9216;                                                  \
      _Pragma("unroll")                                                           \
      for (int ks = 0; ks < 4; ks++) {                                            \
          uint32_t ah[2][4];                                                      \
          _Pragma("unroll")                                                       \
          for (int mi = 0; mi < 2; mi++)                                          \
              ldmx4(ah[mi][0],ah[mi][1],ah[mi][2],ah[mi][3], aH + mi*MI_STEP_B + ks*KS_STEP_B); \
          _Pragma("unroll")                                                       \
          for (int nj2 = 0; nj2 < 2; nj2++) {                                     \
              uint32_t bh[4], bl[4];                                              \
              ldmx4(bh[0],bh[1],bh[2],bh[3], bHo + nj2*MI_STEP_B + ks*KS_STEP_B); \
              ldmx4(bl[0],bl[1],bl[2],bl[3], bLo + nj2*MI_STEP_B + ks*KS_STEP_B); \
              _Pragma("unroll")                                                   \
              for (int jj = 0; jj < 2; jj++) {                                    \
                  int nj = nj2*2 + jj;                                            \
                  _Pragma("unroll")                                               \
                  for (int mi = 0; mi < 2; mi++) {                                \
                      mma16816(acc[mi][nj], ah[mi][0],ah[mi][1],ah[mi][2],ah[mi][3], bh[jj], bh[jj+2]); \
                      mma16816(acc[mi][nj], ah[mi][0],ah[mi][1],ah[mi][2],ah[mi][3], bl[jj], bl[jj+2]); \
                  }                                                               \
              }                                                                   \
          }                                                                       \
      } }

#define LOAD_CHUNK_KV(st, ch)                                                     \
    { uint32_t dst = sb + (st)*ST_WORDS*4;                                        \
      for (int i = tid; i < 1024; i += 256) {                                     \
          int r = i >> 3, c = i & 7;                                              \
          cp16(dst + (r*36 + c*4)*4, gA4h + (size_t)r*64 + (ch)*8 + c);           \
      }                                                                           \
      for (int i = tid; i < 512; i += 256) {                                      \
          int r = i >> 3, c = i & 7;                                              \
          cp16(dst + (4608 + r*36 + c*4)*4, gB4h + (size_t)r*64 + (ch)*8 + c);    \
          cp16(dst + (6912 + r*36 + c*4)*4, gB4l + (size_t)r*64 + (ch)*8 + c);    \
      } }

// ---------------------------------------------------------------------------
// combined split kernels
// ---------------------------------------------------------------------------
#define NX (NB*NS*NDH)
#define NW (NH*NDH*NDH)
__device__ __forceinline__ void split_store4(const float* src, size_t i4,
                                             __half* h, __half* l)
{
    float4 v = ((const float4*)src)[i4];
    uint32_t h0, l0, h1, l1;
    split2(v.x, v.y, h0, l0);
    split2(v.z, v.w, h1, l1);
    *(uint2*)(h + i4*4) = make_uint2(h0, h1);
    *(uint2*)(l + i4*4) = make_uint2(l0, l1);
}
__device__ __forceinline__ void hi_store4(const float* src, size_t i4, __half* h)
{
    float4 v = ((const float4*)src)[i4];
    *(uint2*)(h + i4*4) = make_uint2(pack_h(v.x, v.y), pack_h(v.z, v.w));
}
__global__ void k_split6(const float* __restrict__ xq, const float* __restrict__ xk,
                         const float* __restrict__ xv, const float* __restrict__ wq,
                         const float* __restrict__ wk, const float* __restrict__ wv)
{
    const int NX4 = NX/4, NW4 = NW/4;
    int i = blockIdx.x*256 + threadIdx.x;
    if (i < NX4)                   hi_store4(xq, i, g_Xqh);
    else if (i < 2*NX4)            hi_store4(xk, i - NX4, g_Xkh);
    else if (i < 3*NX4)            hi_store4(xv, i - 2*NX4, g_Xvh);
    else if (i < 3*NX4 + NW4)      split_store4(wq, i - 3*NX4, g_Wqh, g_Wql);
    else if (i < 3*NX4 + 2*NW4)    split_store4(wk, i - 3*NX4 - NW4, g_Wkh, g_Wkl);
    else if (i < 3*NX4 + 3*NW4)    split_store4(wv, i - 3*NX4 - 2*NW4, g_Wvh, g_Wvl);
}
__global__ void k_split3(const float* __restrict__ ew, const float* __restrict__ fw,
                         const float* __restrict__ ow)
{
    const int NE4 = (NT*NS)/4, NO4 = (NDM*NDM)/4;
    int i = blockIdx.x*256 + threadIdx.x;
    if (i < NE4)                   hi_store4(ew, i, g_Ewh);
    else if (i < 2*NE4)            hi_store4(fw, i - NE4, g_Fwh);
    else if (i < 2*NE4 + NO4)      split_store4(ow, i - 2*NE4, g_Owh, g_Owl);
}

// ---------------------------------------------------------------------------
// k_qkv_mma (r14 form)
// ---------------------------------------------------------------------------
__global__ void __launch_bounds__(256, 3) k_qkv_mma(const float* __restrict__ bq,
                                                    const float* __restrict__ bk,
                                                    const float* __restrict__ bv)
{
    extern __shared__ uint32_t sm32[];
    int tid = threadIdx.x, wid = tid >> 5, lane = tid & 31;
    int g = lane >> 2, t4 = lane & 3;
    int m0w = (wid & 3)*32, n0w = (wid >> 2)*32;
    int bh = blockIdx.x, b = bh >> 4, h = bh & 15;
    int s0 = blockIdx.y << 7, z = blockIdx.z;

    uint32_t sb = smem_u32(sm32);
    uint32_t lrow = lane & 15, lsel = (lane >> 4) << 4;

    const uint4 *gA4h, *gB4h, *gB4l;
    const float* bias;
    if (z == 0)      { gA4h = (const uint4*)(g_Xqh + ((size_t)b*NS + s0)*NDH);
                       gB4h = (const uint4*)(g_Wqh + h*4096);
                       gB4l = (const uint4*)(g_Wql + h*4096); bias = bq + h*64; }
    else if (z == 1) { gA4h = (const uint4*)(g_Xkh + ((size_t)b*NS + s0)*NDH);
                       gB4h = (const uint4*)(g_Wkh + h*4096);
                       gB4l = (const uint4*)(g_Wkl + h*4096); bias = bk + h*64; }
    else             { gA4h = (const uint4*)(g_Xvh + ((size_t)b*NS + s0)*NDH);
                       gB4h = (const uint4*)(g_Wvh + h*4096);
                       gB4l = (const uint4*)(g_Wvl + h*4096); bias = bv + h*64; }

    float acc[2][4][4];
#pragma unroll
    for (int mi = 0; mi < 2; mi++)
#pragma unroll
        for (int nj = 0; nj < 4; nj++)
#pragma unroll
            for (int q = 0; q < 4; q++) acc[mi][nj][q] = 0.f;

    for (int i = tid; i < 1024; i += 256) {
        int r = i >> 3, c = i & 7;
        cp16(sb + (r*36 + c*4)*4, gA4h + (size_t)r*8 + c);
    }
    for (int i = tid; i < 512; i += 256) {
        int r = i >> 3, c = i & 7;
        cp16(sb + (4608 + r*36 + c*4)*4, gB4h + (size_t)r*8 + c);
        cp16(sb + (6912 + r*36 + c*4)*4, gB4l + (size_t)r*8 + c);
    }
    cp_wait();
    __syncthreads();
    MMA_CHUNK2(sb);

    if (z == 0) {
        size_t base = (size_t)bh*NS*NDH;
#pragma unroll
        for (int mi = 0; mi < 2; mi++) {
            int m = m0w + mi*16 + g;
#pragma unroll
            for (int nj = 0; nj < 4; nj++) {
                int n = n0w + nj*8 + t4*2;
                float b0 = bias[n], b1 = bias[n + 1];
                size_t i0 = base + (size_t)(s0 + m)*NDH + n;
                *(uint32_t*)(g_Qh + i0) = pack_h(acc[mi][nj][0] + b0, acc[mi][nj][1] + b1);
                size_t i1 = base + (size_t)(s0 + m + 8)*NDH + n;
                *(uint32_t*)(g_Qh + i1) = pack_h(acc[mi][nj][2] + b0, acc[mi][nj][3] + b1);
            }
        }
    } else {
        __syncthreads();
        float* Sg = (float*)sm32;
#pragma unroll
        for (int mi = 0; mi < 2; mi++) {
            int m = m0w + mi*16 + g;
#pragma unroll
            for (int nj = 0; nj < 4; nj++) {
                int n = n0w + nj*8 + t4*2;
                float b0 = bias[n], b1 = bias[n + 1];
                Sg[n*129 + m]         = acc[mi][nj][0] + b0;
                Sg[(n+1)*129 + m]     = acc[mi][nj][1] + b1;
                Sg[n*129 + m + 8]     = acc[mi][nj][2] + b0;
                Sg[(n+1)*129 + m + 8] = acc[mi][nj][3] + b1;
            }
        }
        __syncthreads();
        __half* dh = (z == 1 ? g_Kth : g_Vth);
        __half* dl = (z == 1 ? g_Ktl : g_Vtl);
        size_t base = (size_t)bh*NDH*NS;
        for (int i = tid; i < 4096; i += 256) {
            int d = i >> 6, mm = (i & 63)*2;
            uint32_t hi, lo;
            split2(Sg[d*129 + mm], Sg[d*129 + mm + 1], hi, lo);
            size_t idx = base + (size_t)d*NS + s0 + mm;
            *(uint32_t*)(dh + idx) = hi;
            *(uint32_t*)(dl + idx) = lo;
        }
    }
}

// ---------------------------------------------------------------------------
// k_kevf_mma: merged ke/vf (r15 form, kept — proven win)
// ---------------------------------------------------------------------------
__global__ void __launch_bounds__(256, 3) k_kevf_mma(const float* __restrict__ Eb,
                                                     const float* __restrict__ Fb)
{
    extern __shared__ uint32_t sm32[];
    int tid = threadIdx.x, wid = tid >> 5, lane = tid & 31;
    int g = lane >> 2, t4 = lane & 3;
    int m0w = (wid & 3)*32, n0w = (wid >> 2)*32;
    int bh = blockIdx.x, t0 = blockIdx.y << 7, z = blockIdx.z;

    uint32_t sb = smem_u32(sm32);
    uint32_t lrow = lane & 15, lsel = (lane >> 4) << 4;

    float acc[2][4][4];
#pragma unroll
    for (int mi = 0; mi < 2; mi++)
#pragma unroll
        for (int nj = 0; nj < 4; nj++)
#pragma unroll
            for (int q = 0; q < 4; q++) acc[mi][nj][q] = 0.f;

    const uint4* gA4h = (const uint4*)((z == 0 ? g_Ewh : g_Fwh) + (size_t)t0*NS);
    const uint4* gB4h = (const uint4*)((z == 0 ? g_Kth : g_Vth) + (size_t)bh*NDH*NS);
    const uint4* gB4l = (const uint4*)((z == 0 ? g_Ktl : g_Vtl) + (size_t)bh*NDH*NS);

    LOAD_CHUNK_KV(0, 0);
    cp_commit();
    for (int ch = 0; ch < 8; ch++) {
        if (ch < 7) {
            LOAD_CHUNK_KV((ch+1)&1, ch+1);
            cp_commit();
            cp_waitg1();
        } else cp_waitg0();
        __syncthreads();
        MMA_CHUNK2(sb + (ch&1)*ST_WORDS*4);
        __syncthreads();
    }

    if (z == 0) {
        size_t base = (size_t)bh*NT*NDH;
#pragma unroll
        for (int mi = 0; mi < 2; mi++) {
            int m = m0w + mi*16 + g;
            float e0 = Eb[t0 + m];
            float e1 = Eb[t0 + m + 8];
#pragma unroll
            for (int nj = 0; nj < 4; nj++) {
                int n = n0w + nj*8 + t4*2;
                uint32_t hi, lo;
                size_t i0 = base + (size_t)(t0 + m)*NDH + n;
                split2(acc[mi][nj][0] + e0, acc[mi][nj][1] + e0, hi, lo);
                *(uint32_t*)(g_KEh + i0) = hi;  *(uint32_t*)(g_KEl + i0) = lo;
                size_t i1 = base + (size_t)(t0 + m + 8)*NDH + n;
                split2(acc[mi][nj][2] + e1, acc[mi][nj][3] + e1, hi, lo);
                *(uint32_t*)(g_KEh + i1) = hi;  *(uint32_t*)(g_KEl + i1) = lo;
            }
        }
    } else {
        float* Sg = (float*)sm32;
#pragma unroll
        for (int mi = 0; mi < 2; mi++) {
            int m = m0w + mi*16 + g;
            float f0 = Fb[t0 + m];
            float f1 = Fb[t0 + m + 8];
#pragma unroll
            for (int nj = 0; nj < 4; nj++) {
                int n = n0w + nj*8 + t4*2;
                Sg[n*129 + m]         = acc[mi][nj][0] + f0;
                Sg[(n+1)*129 + m]     = acc[mi][nj][1] + f0;
                Sg[n*129 + m + 8]     = acc[mi][nj][2] + f1;
                Sg[(n+1)*129 + m + 8] = acc[mi][nj][3] + f1;
            }
        }
        __syncthreads();
        size_t base = (size_t)bh*NDH*NT;
        for (int i = tid; i < 4096; i += 256) {
            int d = i >> 6, mm = (i & 63)*2;
            uint32_t hi, lo;
            split2(Sg[d*129 + mm], Sg[d*129 + mm + 1], hi, lo);
            size_t idx = base + (size_t)d*NT + t0 + mm;
            *(uint32_t*)(g_VFth + idx) = hi;
            *(uint32_t*)(g_VFtl + idx) = lo;
        }
    }
}

// ---------------------------------------------------------------------------
// k_attn_fused (EXACT r14 form: 2x256 KE chunks, VF prefetch, fp16 2-term)
// smem (words): KEh@0 (9216) | KEl@9216 | Qh@18432 (1152) | redm@20736 | reds@20992
// ---------------------------------------------------------------------------
#define LOAD_VF(dh, hf, stw)                                                      \
    { for (int i = tid; i < 1024; i += 256) {                                     \
          int r = i >> 5, c = i & 31;                                             \
          cp16(sb + ((stw) + r*132 + c*4)*4,        gVF4h + (size_t)((dh)*32 + r)*64 + (hf)*32 + c); \
          cp16(sb + ((stw) + 4224 + r*132 + c*4)*4, gVF4l + (size_t)((dh)*32 + r)*64 + (hf)*32 + c); \
      } cp_commit(); }

#define PV_COMPUTE(hf, stw)                                                       \
    { uint32_t bH = sb + (stw)*4 + lrow*528 + wid*64 + lsel;                      \
      uint32_t bL = bH + 16896;                                                   \
      _Pragma("unroll")                                                           \
      for (int dt = 0; dt < 2; dt++)                                              \
      _Pragma("unroll")                                                           \
      for (int ks2 = 0; ks2 < 2; ks2++) {                                         \
          int ke = (hf)*2 + ks2;                                                  \
          uint32_t bhv[4], blv[4];                                                \
          ldmx4(bhv[0],bhv[1],bhv[2],bhv[3], bH + dt*8448 + ks2*32);              \
          ldmx4(blv[0],blv[1],blv[2],blv[3], bL + dt*8448 + ks2*32);              \
          _Pragma("unroll")                                                       \
          for (int jj = 0; jj < 2; jj++) {                                        \
              int nd = dt*2 + jj;                                                 \
              _Pragma("unroll")                                                   \
              for (int mi = 0; mi < 2; mi++) {                                    \
                  mma16816(acc_o[mi][nd], pah[ke][mi][0],pah[ke][mi][1],pah[ke][mi][2],pah[ke][mi][3], bhv[jj], bhv[jj+2]); \
                  mma16816(acc_o[mi][nd], pah[ke][mi][0],pah[ke][mi][1],pah[ke][mi][2],pah[ke][mi][3], blv[jj], blv[jj+2]); \
              }                                                                   \
          }                                                                       \
      } }

__global__ void __launch_bounds__(256, 2) k_attn_fused(float* __restrict__ attn_out)
{
    extern __shared__ uint32_t sm32[];
    float* sredm = (float*)(sm32 + 20736);
    float* sreds = (float*)(sm32 + 20992);
    int tid = threadIdx.x, wid = tid >> 5, lane = tid & 31;
    int g = lane >> 2, t4 = lane & 3;
    int s0 = blockIdx.x << 5, bh = blockIdx.y;

    uint32_t sb = smem_u32(sm32);
    uint32_t lrow = lane & 15, lsel = (lane >> 4) << 4;
    uint32_t aoffH = sb + 73728 + lrow*A_STRIDE_B + lsel;
    uint32_t boffH = sb + (wid*32 + lrow)*A_STRIDE_B + lsel;
    uint32_t boffL = boffH + 36864;

    const uint4* gVF4h = (const uint4*)(g_VFth + (size_t)bh*NDH*NT);
    const uint4* gVF4l = (const uint4*)(g_VFtl + (size_t)bh*NDH*NT);

    const uint4* gQ4h = (const uint4*)(g_Qh + ((size_t)bh*NS + s0)*NDH);
    {
        int r = tid >> 3, c = tid & 7;
        cp16(sb + (18432 + r*36 + c*4)*4, gQ4h + (size_t)r*8 + c);
    }

    float acc[2][8][4];
#pragma unroll
    for (int mi = 0; mi < 2; mi++)
#pragma unroll
        for (int nj = 0; nj < 8; nj++)
#pragma unroll
            for (int q = 0; q < 4; q++) acc[mi][nj][q] = 0.f;

    const uint4* gKE4h = (const uint4*)(g_KEh + (size_t)bh*NT*NDH);
    const uint4* gKE4l = (const uint4*)(g_KEl + (size_t)bh*NT*NDH);

    for (int chn = 0; chn < 2; chn++) {
        if (chn) __syncthreads();
        for (int i = tid; i < 2048; i += 256) {
            int r = i >> 3, c = i & 7;
            cp16(sb + (r*36 + c*4)*4,        gKE4h + (size_t)(chn*256 + r)*8 + c);
            cp16(sb + (9216 + r*36 + c*4)*4, gKE4l + (size_t)(chn*256 + r)*8 + c);
        }
        cp_wait();
        __syncthreads();
#pragma unroll
        for (int ks = 0; ks < 4; ks++) {
            uint32_t ah[2][4];
#pragma unroll
            for (int mi = 0; mi < 2; mi++)
                ldmx4(ah[mi][0],ah[mi][1],ah[mi][2],ah[mi][3], aoffH + mi*MI_STEP_B + ks*KS_STEP_B);
#pragma unroll
            for (int nj2 = 0; nj2 < 2; nj2++) {
                uint32_t bhp[4], blp[4];
                ldmx4(bhp[0],bhp[1],bhp[2],bhp[3], boffH + nj2*MI_STEP_B + ks*KS_STEP_B);
                ldmx4(blp[0],blp[1],blp[2],blp[3], boffL + nj2*MI_STEP_B + ks*KS_STEP_B);
#pragma unroll
                for (int jj = 0; jj < 2; jj++) {
                    int nj = chn*4 + nj2*2 + jj;
#pragma unroll
                    for (int mi = 0; mi < 2; mi++) {
                        mma16816(acc[mi][nj], ah[mi][0],ah[mi][1],ah[mi][2],ah[mi][3], bhp[jj], bhp[jj+2]);
                        mma16816(acc[mi][nj], ah[mi][0],ah[mi][1],ah[mi][2],ah[mi][3], blp[jj], blp[jj+2]);
                    }
                }
            }
        }
    }

    __syncthreads();
    LOAD_VF(0, 0, 0);
    LOAD_VF(0, 1, 8448);

    // ---- softmax ----
    float lm[2][2];
#pragma unroll
    for (int mi = 0; mi < 2; mi++) { lm[mi][0] = -1e30f; lm[mi][1] = -1e30f; }
#pragma unroll
    for (int mi = 0; mi < 2; mi++)
#pragma unroll
        for (int nj = 0; nj < 8; nj++) {
#pragma unroll
            for (int q = 0; q < 4; q++) acc[mi][nj][q] *= 0.125f;
            lm[mi][0] = fmaxf(lm[mi][0], fmaxf(acc[mi][nj][0], acc[mi][nj][1]));
            lm[mi][1] = fmaxf(lm[mi][1], fmaxf(acc[mi][nj][2], acc[mi][nj][3]));
        }
#pragma unroll
    for (int mi = 0; mi < 2; mi++)
#pragma unroll
        for (int hh = 0; hh < 2; hh++) {
            lm[mi][hh] = fmaxf(lm[mi][hh], __shfl_xor_sync(0xffffffffu, lm[mi][hh], 1));
            lm[mi][hh] = fmaxf(lm[mi][hh], __shfl_xor_sync(0xffffffffu, lm[mi][hh], 2));
        }
    if (t4 == 0) {
#pragma unroll
        for (int mi = 0; mi < 2; mi++) {
            sredm[wid*32 + mi*16 + g]     = lm[mi][0];
            sredm[wid*32 + mi*16 + g + 8] = lm[mi][1];
        }
    }
    __syncthreads();
    float rowm[2][2];
#pragma unroll
    for (int mi = 0; mi < 2; mi++)
#pragma unroll
        for (int hh = 0; hh < 2; hh++) {
            int row = mi*16 + g + hh*8;
            float m = sredm[row];
#pragma unroll
            for (int w = 1; w < 8; w++) m = fmaxf(m, sredm[w*32 + row]);
            rowm[mi][hh] = m;
        }
    float ls[2][2] = {{0.f,0.f},{0.f,0.f}};
#pragma unroll
    for (int mi = 0; mi < 2; mi++)
#pragma unroll
        for (int nj = 0; nj < 8; nj++) {
            acc[mi][nj][0] = __expf(acc[mi][nj][0] - rowm[mi][0]);
            acc[mi][nj][1] = __expf(acc[mi][nj][1] - rowm[mi][0]);
            acc[mi][nj][2] = __expf(acc[mi][nj][2] - rowm[mi][1]);
            acc[mi][nj][3] = __expf(acc[mi][nj][3] - rowm[mi][1]);
            ls[mi][0] += acc[mi][nj][0] + acc[mi][nj][1];
            ls[mi][1] += acc[mi][nj][2] + acc[mi][nj][3];
        }
#pragma unroll
    for (int mi = 0; mi < 2; mi++)
#pragma unroll
        for (int hh = 0; hh < 2; hh++) {
            ls[mi][hh] += __shfl_xor_sync(0xffffffffu, ls[mi][hh], 1);
            ls[mi][hh] += __shfl_xor_sync(0xffffffffu, ls[mi][hh], 2);
        }
    if (t4 == 0) {
#pragma unroll
        for (int mi = 0; mi < 2; mi++) {
            sreds[wid*32 + mi*16 + g]     = ls[mi][0];
            sreds[wid*32 + mi*16 + g + 8] = ls[mi][1];
        }
    }
    __syncthreads();
    float inv[2][2];
#pragma unroll
    for (int mi = 0; mi < 2; mi++)
#pragma unroll
        for (int hh = 0; hh < 2; hh++) {
            int row = mi*16 + g + hh*8;
            float s = 0.f;
#pragma unroll
            for (int w = 0; w < 8; w++) s += sreds[w*32 + row];
            inv[mi][hh] = 1.f / s;
        }

    uint32_t pah[4][2][4];
#pragma unroll
    for (int hf = 0; hf < 2; hf++)
#pragma unroll
        for (int ks2 = 0; ks2 < 2; ks2++) {
            int ke = hf*2 + ks2;
#pragma unroll
            for (int mi = 0; mi < 2; mi++) {
                int nj0 = hf*4 + ks2*2, nj1 = nj0 + 1;
                size_t r0 = ((size_t)bh*NS + s0 + mi*16 + g)*NT;
                size_t r1 = r0 + 8*NT;
                int c0 = hf*256 + wid*32 + ks2*16 + 2*t4;
                acc[mi][nj0][0] *= inv[mi][0];  acc[mi][nj0][1] *= inv[mi][0];
                acc[mi][nj0][2] *= inv[mi][1];  acc[mi][nj0][3] *= inv[mi][1];
                acc[mi][nj1][0] *= inv[mi][0];  acc[mi][nj1][1] *= inv[mi][0];
                acc[mi][nj1][2] *= inv[mi][1];  acc[mi][nj1][3] *= inv[mi][1];
                __stcs((float2*)(attn_out + r0 + c0),     make_float2(acc[mi][nj0][0], acc[mi][nj0][1]));
                __stcs((float2*)(attn_out + r1 + c0),     make_float2(acc[mi][nj0][2], acc[mi][nj0][3]));
                __stcs((float2*)(attn_out + r0 + c0 + 8), make_float2(acc[mi][nj1][0], acc[mi][nj1][1]));
                __stcs((float2*)(attn_out + r1 + c0 + 8), make_float2(acc[mi][nj1][2], acc[mi][nj1][3]));
                pah[ke][mi][0] = pack_h(acc[mi][nj0][0], acc[mi][nj0][1]);
                pah[ke][mi][1] = pack_h(acc[mi][nj0][2], acc[mi][nj0][3]);
                pah[ke][mi][2] = pack_h(acc[mi][nj1][0], acc[mi][nj1][1]);
                pah[ke][mi][3] = pack_h(acc[mi][nj1][2], acc[mi][nj1][3]);
            }
        }

    for (int dh = 0; dh < 2; dh++) {
        if (dh == 1) {
            LOAD_VF(1, 0, 0);
            LOAD_VF(1, 1, 8448);
        }
        float acc_o[2][4][4];
#pragma unroll
        for (int mi = 0; mi < 2; mi++)
#pragma unroll
            for (int nd = 0; nd < 4; nd++)
#pragma unroll
                for (int q = 0; q < 4; q++) acc_o[mi][nd][q] = 0.f;

        cp_waitg1();
        __syncthreads();
        PV_COMPUTE(0, 0);
        cp_waitg0();
        __syncthreads();
        PV_COMPUTE(1, 8448);

        __syncthreads();
        float* Ob = (float*)sm32;
#pragma unroll
        for (int mi = 0; mi < 2; mi++)
#pragma unroll
            for (int nd = 0; nd < 4; nd++) {
                int m = mi*16 + g, n = nd*8 + 2*t4;
                Ob[wid*1056 + m*33 + n]       = acc_o[mi][nd][0];
                Ob[wid*1056 + m*33 + n + 1]   = acc_o[mi][nd][1];
                Ob[wid*1056 + (m+8)*33 + n]   = acc_o[mi][nd][2];
                Ob[wid*1056 + (m+8)*33 + n+1] = acc_o[mi][nd][3];
            }
        __syncthreads();
        {
            int s = tid >> 3, dg = (tid & 7)*4;
            float o[4] = {0.f, 0.f, 0.f, 0.f};
#pragma unroll
            for (int w = 0; w < 8; w++)
#pragma unroll
                for (int j = 0; j < 4; j++) o[j] += Ob[w*1056 + s*33 + dg + j];
            size_t base = ((size_t)bh*NS + s0 + s)*NDH + dh*32 + dg;
            *(uint32_t*)(g_HOh + base)     = pack_h(o[0], o[1]);
            *(uint32_t*)(g_HOh + base + 2) = pack_h(o[2], o[3]);
        }
        __syncthreads();
    }
}

// ---------------------------------------------------------------------------
// k_out_mma (r14 form)
// ---------------------------------------------------------------------------
__global__ void __launch_bounds__(256, 2) k_out_mma(const float* __restrict__ Ob,
                                                    float* __restrict__ out)
{
    extern __shared__ uint32_t sm32[];
    int tid = threadIdx.x, wid = tid >> 5, lane = tid & 31;
    int g = lane >> 2, t4 = lane & 3;
    int m0w = (wid & 3)*32, n0w = (wid >> 2)*64;
    int n0 = blockIdx.x << 7;
    int m0 = blockIdx.y << 7;
    int b  = blockIdx.y >> 2;
    int sbase = (blockIdx.y & 3) << 7;

    uint32_t sb = smem_u32(sm32);
    uint32_t lrow = lane & 15, lsel = (lane >> 4) << 4;

    float acc[2][8][4];
#pragma unroll
    for (int mi = 0; mi < 2; mi++)
#pragma unroll
        for (int nj = 0; nj < 8; nj++)
#pragma unroll
            for (int q = 0; q < 4; q++) acc[mi][nj][q] = 0.f;

    const uint4* gB4h = (const uint4*)(g_Owh + (size_t)n0*NDM);
    const uint4* gB4l = (const uint4*)(g_Owl + (size_t)n0*NDM);

#define LOAD_CHUNK_OUT(st, kc)                                                    \
    { uint32_t dst = sb + (st)*55296;                                             \
      const uint4* gA4h = (const uint4*)(g_HOh + ((size_t)(b*NH + (kc))*NS + sbase)*NDH); \
      for (int i = tid; i < 1024; i += 256) {                                     \
          int r = i >> 3, c = i & 7;                                              \
          cp16(dst + (r*36 + c*4)*4, gA4h + (size_t)r*8 + c);                     \
      }                                                                           \
      for (int i = tid; i < 1024; i += 256) {                                     \
          int r = i >> 3, c = i & 7;                                              \
          cp16(dst + (4608 + r*36 + c*4)*4, gB4h + (size_t)r*128 + (kc)*8 + c);   \
          cp16(dst + (9216 + r*36 + c*4)*4, gB4l + (size_t)r*128 + (kc)*8 + c);   \
      } }

    LOAD_CHUNK_OUT(0, 0);
    cp_commit();
    for (int kc = 0; kc < 16; kc++) {
        if (kc < 15) {
            LOAD_CHUNK_OUT((kc+1)&1, kc+1);
            cp_commit();
            cp_waitg1();
        } else cp_waitg0();
        __syncthreads();
        uint32_t bu = sb + (kc&1)*55296;
        uint32_t aH  = bu + (m0w + lrow)*A_STRIDE_B + lsel;
        uint32_t bHo = bu + 18432 + (n0w + lrow)*A_STRIDE_B + lsel;
        uint32_t bLo = bHo + 18432;
#pragma unroll
        for (int ks = 0; ks < 4; ks++) {
            uint32_t ah[2][4];
#pragma unroll
            for (int mi = 0; mi < 2; mi++)
                ldmx4(ah[mi][0],ah[mi][1],ah[mi][2],ah[mi][3], aH + mi*MI_STEP_B + ks*KS_STEP_B);
#pragma unroll
            for (int nj2 = 0; nj2 < 4; nj2++) {
                uint32_t bh[4], bl[4];
                ldmx4(bh[0],bh[1],bh[2],bh[3], bHo + nj2*MI_STEP_B + ks*KS_STEP_B);
                ldmx4(bl[0],bl[1],bl[2],bl[3], bLo + nj2*MI_STEP_B + ks*KS_STEP_B);
#pragma unroll
                for (int jj = 0; jj < 2; jj++) {
                    int nj = nj2*2 + jj;
#pragma unroll
                    for (int mi = 0; mi < 2; mi++) {
                        mma16816(acc[mi][nj], ah[mi][0],ah[mi][1],ah[mi][2],ah[mi][3], bh[jj], bh[jj+2]);
                        mma16816(acc[mi][nj], ah[mi][0],ah[mi][1],ah[mi][2],ah[mi][3], bl[jj], bl[jj+2]);
                    }
                }
            }
        }
        __syncthreads();
    }

    float* Sg = (float*)sm32;
#pragma unroll
    for (int mi = 0; mi < 2; mi++) {
        int m = m0w + mi*16 + g;
#pragma unroll
        for (int nj = 0; nj < 8; nj++) {
            int n = n0w + nj*8 + t4*2;
            float o0 = Ob[n0 + n];
            float o1 = Ob[n0 + n + 1];
            Sg[m*129 + n]         = acc[mi][nj][0] + o0;
            Sg[m*129 + n + 1]     = acc[mi][nj][1] + o1;
            Sg[(m+8)*129 + n]     = acc[mi][nj][2] + o0;
            Sg[(m+8)*129 + n + 1] = acc[mi][nj][3] + o1;
        }
    }
    __syncthreads();
    for (int i = tid; i < 4096; i += 256) {
        int r = i >> 5, c4 = (i & 31)*4;
        float4 v = make_float4(Sg[r*129 + c4], Sg[r*129 + c4 + 1],
                               Sg[r*129 + c4 + 2], Sg[r*129 + c4 + 3]);
        __stcs((float4*)(out + (size_t)(m0 + r)*NDM + n0 + c4), v);
    }
}

// ---------------------------------------------------------------------------
extern "C" void kernel_launch(void* const* d_in, const int* in_sizes, int n_in,
                              void* d_out, int out_size)
{
    const float* query = (const float*)d_in[0];
    const float* key   = (const float*)d_in[1];
    const float* value = (const float*)d_in[2];
    const float* Wq    = (const float*)d_in[3];
    const float* bq    = (const float*)d_in[4];
    const float* Wk    = (const float*)d_in[5];
    const float* bk    = (const float*)d_in[6];
    const float* Wv    = (const float*)d_in[7];
    const float* bv    = (const float*)d_in[8];
    const float* E_w   = (const float*)d_in[9];
    const float* E_b   = (const float*)d_in[10];
    const float* F_w   = (const float*)d_in[11];
    const float* F_b   = (const float*)d_in[12];
    const float* out_w = (const float*)d_in[13];
    const float* out_b = (const float*)d_in[14];

    const long long mha_elems  = (long long)NB*NS*NDM;
    const long long attn_elems = (long long)BH*NS*NT;

    float* outp = (float*)d_out;
    float* mha_ptr;
    float* attn_ptr;
    if ((long long)out_size >= mha_elems + attn_elems) {
        mha_ptr  = outp;
        attn_ptr = outp + mha_elems;
    } else if ((long long)out_size == attn_elems) {
        attn_ptr = outp;
        cudaGetSymbolAddress((void**)&mha_ptr, g_MHA_FB);
    } else {
        mha_ptr = outp;
        cudaGetSymbolAddress((void**)&attn_ptr, g_ATTN_FB);
    }

    cudaFuncSetAttribute(k_qkv_mma,    cudaFuncAttributeMaxDynamicSharedMemorySize, 36864);
    cudaFuncSetAttribute(k_kevf_mma,   cudaFuncAttributeMaxDynamicSharedMemorySize, 73728);
    cudaFuncSetAttribute(k_out_mma,    cudaFuncAttributeMaxDynamicSharedMemorySize, 110592);
    cudaFuncSetAttribute(k_attn_fused, cudaFuncAttributeMaxDynamicSharedMemorySize, 84992);

    k_split6<<<((3*NX + 3*NW)/4 + 255)/256, 256>>>(query, key, value, Wq, Wk, Wv);
    k_split3<<<((2*NT*NS + NDM*NDM)/4 + 255)/256, 256>>>(E_w, F_w, out_w);
    k_qkv_mma<<<dim3(BH, 4, 3), 256, 36864>>>(bq, bk, bv);
    k_kevf_mma<<<dim3(BH, 4, 2), 256, 73728>>>(E_b, F_b);
    k_attn_fused<<<dim3(16, BH), 256, 84992>>>(attn_ptr);
    k_out_mma<<<dim3(NDM/128, (NB*NS)/128), 256, 110592>>>(out_b, mha_ptr);
}

// round 17
// speedup vs baseline: 1.4390x; 1.4129x over previous
#include <cuda_runtime.h>
#include <cuda_fp16.h>
#include <cstdint>

#define NB 32
#define NS 512
#define NH 16
#define NDH 64
#define NDM 1024
#define NT 512
#define BH (NB*NH)

// ---------------- global scratch (pure fp16, hi-only everywhere) ----------
__device__ __half g_Xqh[NB*NS*NDH];
__device__ __half g_Xkh[NB*NS*NDH];
__device__ __half g_Xvh[NB*NS*NDH];
__device__ __half g_Wqh[NH*NDH*NDH];
__device__ __half g_Wkh[NH*NDH*NDH];
__device__ __half g_Wvh[NH*NDH*NDH];
__device__ __half g_Qh [(size_t)BH*NS*NDH];
__device__ __half g_Kth[(size_t)BH*NDH*NS];
__device__ __half g_Vth[(size_t)BH*NDH*NS];
__device__ __half g_KEh[(size_t)BH*NT*NDH];
__device__ __half g_VFth[(size_t)BH*NDH*NT];
__device__ __half g_Ewh[NT*NS];
__device__ __half g_Fwh[NT*NS];
__device__ __half g_Owh[NDM*NDM];
__device__ __half g_HOh[(size_t)BH*NS*NDH];
__device__ float g_ATTN_FB[(size_t)BH*NS*NT];
__device__ float g_MHA_FB [(size_t)NB*NS*NDM];

// ---------------- helpers ----------------
__device__ __forceinline__ uint32_t smem_u32(const void* p) {
    uint32_t a;
    asm("{ .reg .u64 t; cvta.to.shared.u64 t, %1; cvt.u32.u64 %0, t; }" : "=r"(a) : "l"(p));
    return a;
}
__device__ __forceinline__ void mma16816(float c[4],
                                         uint32_t a0, uint32_t a1, uint32_t a2, uint32_t a3,
                                         uint32_t b0, uint32_t b1)
{
    asm volatile(
        "mma.sync.aligned.m16n8k16.row.col.f32.f16.f16.f32 "
        "{%0,%1,%2,%3}, {%4,%5,%6,%7}, {%8,%9}, {%0,%1,%2,%3};"
        : "+f"(c[0]), "+f"(c[1]), "+f"(c[2]), "+f"(c[3])
        : "r"(a0), "r"(a1), "r"(a2), "r"(a3), "r"(b0), "r"(b1));
}
__device__ __forceinline__ void ldmx4(uint32_t& r0, uint32_t& r1, uint32_t& r2, uint32_t& r3,
                                      uint32_t addr)
{
    asm volatile("ldmatrix.sync.aligned.m8n8.x4.shared.b16 {%0,%1,%2,%3}, [%4];"
                 : "=r"(r0), "=r"(r1), "=r"(r2), "=r"(r3) : "r"(addr));
}
__device__ __forceinline__ void cp16(uint32_t saddr, const void* g)
{
    asm volatile("cp.async.cg.shared.global [%0], [%1], 16;" :: "r"(saddr), "l"(g) : "memory");
}
__device__ __forceinline__ void cp_commit() { asm volatile("cp.async.commit_group;" ::: "memory"); }
__device__ __forceinline__ void cp_waitg1() { asm volatile("cp.async.wait_group 1;" ::: "memory"); }
__device__ __forceinline__ void cp_waitg0() { asm volatile("cp.async.wait_group 0;" ::: "memory"); }
__device__ __forceinline__ void cp_wait()
{
    asm volatile("cp.async.commit_group;\n\tcp.async.wait_group 0;" ::: "memory");
}
__device__ __forceinline__ uint32_t pack_h(float x, float y)
{
    __half2 h = __floats2half2_rn(x, y);
    return *(uint32_t*)&h;
}

// smem geometry: rows padded to 144B
#define A_STRIDE_B 144
#define MI_STEP_B  2304
#define KS_STEP_B  32

// pure fp16 chunk (k=64): D += Ah·Bh.  Stage (words):
// Ah@0 (128x36=4608) | Bh@4608 (64x36=2304) -> 6912 words/stage (27648 B)
#define ST_WORDS 6912
#define MMA_CHUNK1(bu)                                                            \
    { uint32_t aH  = (bu) + (m0w + lrow)*A_STRIDE_B + lsel;                       \
      uint32_t bHo = (bu) + 18432 + (n0w + lrow)*A_STRIDE_B + lsel;               \
      _Pragma("unroll")                                                           \
      for (int ks = 0; ks < 4; ks++) {                                            \
          uint32_t ah[2][4];                                                      \
          _Pragma("unroll")                                                       \
          for (int mi = 0; mi < 2; mi++)                                          \
              ldmx4(ah[mi][0],ah[mi][1],ah[mi][2],ah[mi][3], aH + mi*MI_STEP_B + ks*KS_STEP_B); \
          _Pragma("unroll")                                                       \
          for (int nj2 = 0; nj2 < 2; nj2++) {                                     \
              uint32_t bh[4];                                                     \
              ldmx4(bh[0],bh[1],bh[2],bh[3], bHo + nj2*MI_STEP_B + ks*KS_STEP_B); \
              _Pragma("unroll")                                                   \
              for (int jj = 0; jj < 2; jj++) {                                    \
                  int nj = nj2*2 + jj;                                            \
                  _Pragma("unroll")                                               \
                  for (int mi = 0; mi < 2; mi++)                                  \
                      mma16816(acc[mi][nj], ah[mi][0],ah[mi][1],ah[mi][2],ah[mi][3], bh[jj], bh[jj+2]); \
              }                                                                   \
          }                                                                       \
      } }

#define LOAD_CHUNK_KV(st, ch)                                                     \
    { uint32_t dst = sb + (st)*ST_WORDS*4;                                        \
      for (int i = tid; i < 1024; i += 256) {                                     \
          int r = i >> 3, c = i & 7;                                              \
          cp16(dst + (r*36 + c*4)*4, gA4h + (size_t)r*64 + (ch)*8 + c);           \
      }                                                                           \
      for (int i = tid; i < 512; i += 256) {                                      \
          int r = i >> 3, c = i & 7;                                              \
          cp16(dst + (4608 + r*36 + c*4)*4, gB4h + (size_t)r*64 + (ch)*8 + c);    \
      } }

// ---------------------------------------------------------------------------
// combined split kernels (all hi-only now)
// ---------------------------------------------------------------------------
#define NX (NB*NS*NDH)
#define NW (NH*NDH*NDH)
__device__ __forceinline__ void hi_store4(const float* src, size_t i4, __half* h)
{
    float4 v = ((const float4*)src)[i4];
    *(uint2*)(h + i4*4) = make_uint2(pack_h(v.x, v.y), pack_h(v.z, v.w));
}
__global__ void k_split6(const float* __restrict__ xq, const float* __restrict__ xk,
                         const float* __restrict__ xv, const float* __restrict__ wq,
                         const float* __restrict__ wk, const float* __restrict__ wv)
{
    const int NX4 = NX/4, NW4 = NW/4;
    int i = blockIdx.x*256 + threadIdx.x;
    if (i < NX4)                   hi_store4(xq, i, g_Xqh);
    else if (i < 2*NX4)            hi_store4(xk, i - NX4, g_Xkh);
    else if (i < 3*NX4)            hi_store4(xv, i - 2*NX4, g_Xvh);
    else if (i < 3*NX4 + NW4)      hi_store4(wq, i - 3*NX4, g_Wqh);
    else if (i < 3*NX4 + 2*NW4)    hi_store4(wk, i - 3*NX4 - NW4, g_Wkh);
    else if (i < 3*NX4 + 3*NW4)    hi_store4(wv, i - 3*NX4 - 2*NW4, g_Wvh);
}
__global__ void k_split3(const float* __restrict__ ew, const float* __restrict__ fw,
                         const float* __restrict__ ow)
{
    const int NE4 = (NT*NS)/4, NO4 = (NDM*NDM)/4;
    int i = blockIdx.x*256 + threadIdx.x;
    if (i < NE4)                   hi_store4(ew, i, g_Ewh);
    else if (i < 2*NE4)            hi_store4(fw, i - NE4, g_Fwh);
    else if (i < 2*NE4 + NO4)      hi_store4(ow, i - 2*NE4, g_Owh);
}

// ---------------------------------------------------------------------------
// k_qkv_mma: single chunk, pure fp16. smem 36864
// ---------------------------------------------------------------------------
__global__ void __launch_bounds__(256, 3) k_qkv_mma(const float* __restrict__ bq,
                                                    const float* __restrict__ bk,
                                                    const float* __restrict__ bv)
{
    extern __shared__ uint32_t sm32[];
    int tid = threadIdx.x, wid = tid >> 5, lane = tid & 31;
    int g = lane >> 2, t4 = lane & 3;
    int m0w = (wid & 3)*32, n0w = (wid >> 2)*32;
    int bh = blockIdx.x, b = bh >> 4, h = bh & 15;
    int s0 = blockIdx.y << 7, z = blockIdx.z;

    uint32_t sb = smem_u32(sm32);
    uint32_t lrow = lane & 15, lsel = (lane >> 4) << 4;

    const uint4 *gA4h, *gB4h;
    const float* bias;
    if (z == 0)      { gA4h = (const uint4*)(g_Xqh + ((size_t)b*NS + s0)*NDH);
                       gB4h = (const uint4*)(g_Wqh + h*4096); bias = bq + h*64; }
    else if (z == 1) { gA4h = (const uint4*)(g_Xkh + ((size_t)b*NS + s0)*NDH);
                       gB4h = (const uint4*)(g_Wkh + h*4096); bias = bk + h*64; }
    else             { gA4h = (const uint4*)(g_Xvh + ((size_t)b*NS + s0)*NDH);
                       gB4h = (const uint4*)(g_Wvh + h*4096); bias = bv + h*64; }

    float acc[2][4][4];
#pragma unroll
    for (int mi = 0; mi < 2; mi++)
#pragma unroll
        for (int nj = 0; nj < 4; nj++)
#pragma unroll
            for (int q = 0; q < 4; q++) acc[mi][nj][q] = 0.f;

    for (int i = tid; i < 1024; i += 256) {
        int r = i >> 3, c = i & 7;
        cp16(sb + (r*36 + c*4)*4, gA4h + (size_t)r*8 + c);
    }
    for (int i = tid; i < 512; i += 256) {
        int r = i >> 3, c = i & 7;
        cp16(sb + (4608 + r*36 + c*4)*4, gB4h + (size_t)r*8 + c);
    }
    cp_wait();
    __syncthreads();
    MMA_CHUNK1(sb);

    if (z == 0) {
        size_t base = (size_t)bh*NS*NDH;
#pragma unroll
        for (int mi = 0; mi < 2; mi++) {
            int m = m0w + mi*16 + g;
#pragma unroll
            for (int nj = 0; nj < 4; nj++) {
                int n = n0w + nj*8 + t4*2;
                float b0 = bias[n], b1 = bias[n + 1];
                size_t i0 = base + (size_t)(s0 + m)*NDH + n;
                *(uint32_t*)(g_Qh + i0) = pack_h(acc[mi][nj][0] + b0, acc[mi][nj][1] + b1);
                size_t i1 = base + (size_t)(s0 + m + 8)*NDH + n;
                *(uint32_t*)(g_Qh + i1) = pack_h(acc[mi][nj][2] + b0, acc[mi][nj][3] + b1);
            }
        }
    } else {
        __syncthreads();
        float* Sg = (float*)sm32;
#pragma unroll
        for (int mi = 0; mi < 2; mi++) {
            int m = m0w + mi*16 + g;
#pragma unroll
            for (int nj = 0; nj < 4; nj++) {
                int n = n0w + nj*8 + t4*2;
                float b0 = bias[n], b1 = bias[n + 1];
                Sg[n*129 + m]         = acc[mi][nj][0] + b0;
                Sg[(n+1)*129 + m]     = acc[mi][nj][1] + b1;
                Sg[n*129 + m + 8]     = acc[mi][nj][2] + b0;
                Sg[(n+1)*129 + m + 8] = acc[mi][nj][3] + b1;
            }
        }
        __syncthreads();
        __half* dh = (z == 1 ? g_Kth : g_Vth);
        size_t base = (size_t)bh*NDH*NS;
        for (int i = tid; i < 4096; i += 256) {
            int d = i >> 6, mm = (i & 63)*2;
            size_t idx = base + (size_t)d*NS + s0 + mm;
            *(uint32_t*)(dh + idx) = pack_h(Sg[d*129 + mm], Sg[d*129 + mm + 1]);
        }
    }
}

// ---------------------------------------------------------------------------
// k_kevf_mma: merged ke/vf, 8 chunks double-buffered, occ 3, smem 55296
// ---------------------------------------------------------------------------
__global__ void __launch_bounds__(256, 3) k_kevf_mma(const float* __restrict__ Eb,
                                                     const float* __restrict__ Fb)
{
    extern __shared__ uint32_t sm32[];
    int tid = threadIdx.x, wid = tid >> 5, lane = tid & 31;
    int g = lane >> 2, t4 = lane & 3;
    int m0w = (wid & 3)*32, n0w = (wid >> 2)*32;
    int bh = blockIdx.x, t0 = blockIdx.y << 7, z = blockIdx.z;

    uint32_t sb = smem_u32(sm32);
    uint32_t lrow = lane & 15, lsel = (lane >> 4) << 4;

    float acc[2][4][4];
#pragma unroll
    for (int mi = 0; mi < 2; mi++)
#pragma unroll
        for (int nj = 0; nj < 4; nj++)
#pragma unroll
            for (int q = 0; q < 4; q++) acc[mi][nj][q] = 0.f;

    const uint4* gA4h = (const uint4*)((z == 0 ? g_Ewh : g_Fwh) + (size_t)t0*NS);
    const uint4* gB4h = (const uint4*)((z == 0 ? g_Kth : g_Vth) + (size_t)bh*NDH*NS);

    LOAD_CHUNK_KV(0, 0);
    cp_commit();
    for (int ch = 0; ch < 8; ch++) {
        if (ch < 7) {
            LOAD_CHUNK_KV((ch+1)&1, ch+1);
            cp_commit();
            cp_waitg1();
        } else cp_waitg0();
        __syncthreads();
        MMA_CHUNK1(sb + (ch&1)*ST_WORDS*4);
        __syncthreads();
    }

    if (z == 0) {
        size_t base = (size_t)bh*NT*NDH;
#pragma unroll
        for (int mi = 0; mi < 2; mi++) {
            int m = m0w + mi*16 + g;
            float e0 = Eb[t0 + m];
            float e1 = Eb[t0 + m + 8];
#pragma unroll
            for (int nj = 0; nj < 4; nj++) {
                int n = n0w + nj*8 + t4*2;
                size_t i0 = base + (size_t)(t0 + m)*NDH + n;
                *(uint32_t*)(g_KEh + i0) = pack_h(acc[mi][nj][0] + e0, acc[mi][nj][1] + e0);
                size_t i1 = base + (size_t)(t0 + m + 8)*NDH + n;
                *(uint32_t*)(g_KEh + i1) = pack_h(acc[mi][nj][2] + e1, acc[mi][nj][3] + e1);
            }
        }
    } else {
        float* Sg = (float*)sm32;
#pragma unroll
        for (int mi = 0; mi < 2; mi++) {
            int m = m0w + mi*16 + g;
            float f0 = Fb[t0 + m];
            float f1 = Fb[t0 + m + 8];
#pragma unroll
            for (int nj = 0; nj < 4; nj++) {
                int n = n0w + nj*8 + t4*2;
                Sg[n*129 + m]         = acc[mi][nj][0] + f0;
                Sg[(n+1)*129 + m]     = acc[mi][nj][1] + f0;
                Sg[n*129 + m + 8]     = acc[mi][nj][2] + f1;
                Sg[(n+1)*129 + m + 8] = acc[mi][nj][3] + f1;
            }
        }
        __syncthreads();
        size_t base = (size_t)bh*NDH*NT;
        for (int i = tid; i < 4096; i += 256) {
            int d = i >> 6, mm = (i & 63)*2;
            size_t idx = base + (size_t)d*NT + t0 + mm;
            *(uint32_t*)(g_VFth + idx) = pack_h(Sg[d*129 + mm], Sg[d*129 + mm + 1]);
        }
    }
}

// ---------------------------------------------------------------------------
// k_attn_fused: pure fp16. smem (words): KEh@0 (9216) | Qh@9216 (1152) |
// redm@10368 (256) | reds@10624 (256) -> 10880 w = 43520 B, occ 2.
// VF stages overlay KE region: stage0@0 (4224 w), stage1@4224.
// ---------------------------------------------------------------------------
#define LOAD_VF(dh, hf, stw)                                                      \
    { for (int i = tid; i < 1024; i += 256) {                                     \
          int r = i >> 5, c = i & 31;                                             \
          cp16(sb + ((stw) + r*132 + c*4)*4, gVF4h + (size_t)((dh)*32 + r)*64 + (hf)*32 + c); \
      } cp_commit(); }

#define PV_COMPUTE(hf, stw)                                                       \
    { uint32_t bH = sb + (stw)*4 + lrow*528 + wid*64 + lsel;                      \
      _Pragma("unroll")                                                           \
      for (int dt = 0; dt < 2; dt++)                                              \
      _Pragma("unroll")                                                           \
      for (int ks2 = 0; ks2 < 2; ks2++) {                                         \
          int ke = (hf)*2 + ks2;                                                  \
          uint32_t bhv[4];                                                        \
          ldmx4(bhv[0],bhv[1],bhv[2],bhv[3], bH + dt*8448 + ks2*32);              \
          _Pragma("unroll")                                                       \
          for (int jj = 0; jj < 2; jj++) {                                        \
              int nd = dt*2 + jj;                                                 \
              _Pragma("unroll")                                                   \
              for (int mi = 0; mi < 2; mi++)                                      \
                  mma16816(acc_o[mi][nd], pah[ke][mi][0],pah[ke][mi][1],pah[ke][mi][2],pah[ke][mi][3], bhv[jj], bhv[jj+2]); \
          }                                                                       \
      } }

__global__ void __launch_bounds__(256, 2) k_attn_fused(float* __restrict__ attn_out)
{
    extern __shared__ uint32_t sm32[];
    float* sredm = (float*)(sm32 + 10368);
    float* sreds = (float*)(sm32 + 10624);
    int tid = threadIdx.x, wid = tid >> 5, lane = tid & 31;
    int g = lane >> 2, t4 = lane & 3;
    int s0 = blockIdx.x << 5, bh = blockIdx.y;

    uint32_t sb = smem_u32(sm32);
    uint32_t lrow = lane & 15, lsel = (lane >> 4) << 4;
    uint32_t aoffH = sb + 36864 + lrow*A_STRIDE_B + lsel;    // Q @ word 9216
    uint32_t boffH = sb + (wid*32 + lrow)*A_STRIDE_B + lsel;

    const uint4* gVF4h = (const uint4*)(g_VFth + (size_t)bh*NDH*NT);
    const uint4* gKE4h = (const uint4*)(g_KEh + (size_t)bh*NT*NDH);
    const uint4* gQ4h  = (const uint4*)(g_Qh + ((size_t)bh*NS + s0)*NDH);

    {
        int r = tid >> 3, c = tid & 7;
        cp16(sb + (9216 + r*36 + c*4)*4, gQ4h + (size_t)r*8 + c);
    }

    float acc[2][8][4];
#pragma unroll
    for (int mi = 0; mi < 2; mi++)
#pragma unroll
        for (int nj = 0; nj < 8; nj++)
#pragma unroll
            for (int q = 0; q < 4; q++) acc[mi][nj][q] = 0.f;

    for (int chn = 0; chn < 2; chn++) {
        if (chn) __syncthreads();
        for (int i = tid; i < 2048; i += 256) {
            int r = i >> 3, c = i & 7;
            cp16(sb + (r*36 + c*4)*4, gKE4h + (size_t)(chn*256 + r)*8 + c);
        }
        cp_wait();
        __syncthreads();
#pragma unroll
        for (int ks = 0; ks < 4; ks++) {
            uint32_t ah[2][4];
#pragma unroll
            for (int mi = 0; mi < 2; mi++)
                ldmx4(ah[mi][0],ah[mi][1],ah[mi][2],ah[mi][3], aoffH + mi*MI_STEP_B + ks*KS_STEP_B);
#pragma unroll
            for (int nj2 = 0; nj2 < 2; nj2++) {
                uint32_t bhp[4];
                ldmx4(bhp[0],bhp[1],bhp[2],bhp[3], boffH + nj2*MI_STEP_B + ks*KS_STEP_B);
#pragma unroll
                for (int jj = 0; jj < 2; jj++) {
                    int nj = chn*4 + nj2*2 + jj;
#pragma unroll
                    for (int mi = 0; mi < 2; mi++)
                        mma16816(acc[mi][nj], ah[mi][0],ah[mi][1],ah[mi][2],ah[mi][3], bhp[jj], bhp[jj+2]);
                }
            }
        }
    }

    __syncthreads();
    LOAD_VF(0, 0, 0);
    LOAD_VF(0, 1, 4224);

    // ---- softmax ----
    float lm[2][2];
#pragma unroll
    for (int mi = 0; mi < 2; mi++) { lm[mi][0] = -1e30f; lm[mi][1] = -1e30f; }
#pragma unroll
    for (int mi = 0; mi < 2; mi++)
#pragma unroll
        for (int nj = 0; nj < 8; nj++) {
#pragma unroll
            for (int q = 0; q < 4; q++) acc[mi][nj][q] *= 0.125f;
            lm[mi][0] = fmaxf(lm[mi][0], fmaxf(acc[mi][nj][0], acc[mi][nj][1]));
            lm[mi][1] = fmaxf(lm[mi][1], fmaxf(acc[mi][nj][2], acc[mi][nj][3]));
        }
#pragma unroll
    for (int mi = 0; mi < 2; mi++)
#pragma unroll
        for (int hh = 0; hh < 2; hh++) {
            lm[mi][hh] = fmaxf(lm[mi][hh], __shfl_xor_sync(0xffffffffu, lm[mi][hh], 1));
            lm[mi][hh] = fmaxf(lm[mi][hh], __shfl_xor_sync(0xffffffffu, lm[mi][hh], 2));
        }
    if (t4 == 0) {
#pragma unroll
        for (int mi = 0; mi < 2; mi++) {
            sredm[wid*32 + mi*16 + g]     = lm[mi][0];
            sredm[wid*32 + mi*16 + g + 8] = lm[mi][1];
        }
    }
    __syncthreads();
    float rowm[2][2];
#pragma unroll
    for (int mi = 0; mi < 2; mi++)
#pragma unroll
        for (int hh = 0; hh < 2; hh++) {
            int row = mi*16 + g + hh*8;
            float m = sredm[row];
#pragma unroll
            for (int w = 1; w < 8; w++) m = fmaxf(m, sredm[w*32 + row]);
            rowm[mi][hh] = m;
        }
    float ls[2][2] = {{0.f,0.f},{0.f,0.f}};
#pragma unroll
    for (int mi = 0; mi < 2; mi++)
#pragma unroll
        for (int nj = 0; nj < 8; nj++) {
            acc[mi][nj][0] = __expf(acc[mi][nj][0] - rowm[mi][0]);
            acc[mi][nj][1] = __expf(acc[mi][nj][1] - rowm[mi][0]);
            acc[mi][nj][2] = __expf(acc[mi][nj][2] - rowm[mi][1]);
            acc[mi][nj][3] = __expf(acc[mi][nj][3] - rowm[mi][1]);
            ls[mi][0] += acc[mi][nj][0] + acc[mi][nj][1];
            ls[mi][1] += acc[mi][nj][2] + acc[mi][nj][3];
        }
#pragma unroll
    for (int mi = 0; mi < 2; mi++)
#pragma unroll
        for (int hh = 0; hh < 2; hh++) {
            ls[mi][hh] += __shfl_xor_sync(0xffffffffu, ls[mi][hh], 1);
            ls[mi][hh] += __shfl_xor_sync(0xffffffffu, ls[mi][hh], 2);
        }
    if (t4 == 0) {
#pragma unroll
        for (int mi = 0; mi < 2; mi++) {
            sreds[wid*32 + mi*16 + g]     = ls[mi][0];
            sreds[wid*32 + mi*16 + g + 8] = ls[mi][1];
        }
    }
    __syncthreads();
    float inv[2][2];
#pragma unroll
    for (int mi = 0; mi < 2; mi++)
#pragma unroll
        for (int hh = 0; hh < 2; hh++) {
            int row = mi*16 + g + hh*8;
            float s = 0.f;
#pragma unroll
            for (int w = 0; w < 8; w++) s += sreds[w*32 + row];
            inv[mi][hh] = 1.f / s;
        }

    uint32_t pah[4][2][4];
#pragma unroll
    for (int hf = 0; hf < 2; hf++)
#pragma unroll
        for (int ks2 = 0; ks2 < 2; ks2++) {
            int ke = hf*2 + ks2;
#pragma unroll
            for (int mi = 0; mi < 2; mi++) {
                int nj0 = hf*4 + ks2*2, nj1 = nj0 + 1;
                size_t r0 = ((size_t)bh*NS + s0 + mi*16 + g)*NT;
                size_t r1 = r0 + 8*NT;
                int c0 = hf*256 + wid*32 + ks2*16 + 2*t4;
                acc[mi][nj0][0] *= inv[mi][0];  acc[mi][nj0][1] *= inv[mi][0];
                acc[mi][nj0][2] *= inv[mi][1];  acc[mi][nj0][3] *= inv[mi][1];
                acc[mi][nj1][0] *= inv[mi][0];  acc[mi][nj1][1] *= inv[mi][0];
                acc[mi][nj1][2] *= inv[mi][1];  acc[mi][nj1][3] *= inv[mi][1];
                __stcs((float2*)(attn_out + r0 + c0),     make_float2(acc[mi][nj0][0], acc[mi][nj0][1]));
                __stcs((float2*)(attn_out + r1 + c0),     make_float2(acc[mi][nj0][2], acc[mi][nj0][3]));
                __stcs((float2*)(attn_out + r0 + c0 + 8), make_float2(acc[mi][nj1][0], acc[mi][nj1][1]));
                __stcs((float2*)(attn_out + r1 + c0 + 8), make_float2(acc[mi][nj1][2], acc[mi][nj1][3]));
                pah[ke][mi][0] = pack_h(acc[mi][nj0][0], acc[mi][nj0][1]);
                pah[ke][mi][1] = pack_h(acc[mi][nj0][2], acc[mi][nj0][3]);
                pah[ke][mi][2] = pack_h(acc[mi][nj1][0], acc[mi][nj1][1]);
                pah[ke][mi][3] = pack_h(acc[mi][nj1][2], acc[mi][nj1][3]);
            }
        }

    for (int dh = 0; dh < 2; dh++) {
        if (dh == 1) {
            LOAD_VF(1, 0, 0);
            LOAD_VF(1, 1, 4224);
        }
        float acc_o[2][4][4];
#pragma unroll
        for (int mi = 0; mi < 2; mi++)
#pragma unroll
            for (int nd = 0; nd < 4; nd++)
#pragma unroll
                for (int q = 0; q < 4; q++) acc_o[mi][nd][q] = 0.f;

        cp_waitg1();
        __syncthreads();
        PV_COMPUTE(0, 0);
        cp_waitg0();
        __syncthreads();
        PV_COMPUTE(1, 4224);

        __syncthreads();
        float* Ob = (float*)sm32;
#pragma unroll
        for (int mi = 0; mi < 2; mi++)
#pragma unroll
            for (int nd = 0; nd < 4; nd++) {
                int m = mi*16 + g, n = nd*8 + 2*t4;
                Ob[wid*1056 + m*33 + n]       = acc_o[mi][nd][0];
                Ob[wid*1056 + m*33 + n + 1]   = acc_o[mi][nd][1];
                Ob[wid*1056 + (m+8)*33 + n]   = acc_o[mi][nd][2];
                Ob[wid*1056 + (m+8)*33 + n+1] = acc_o[mi][nd][3];
            }
        __syncthreads();
        {
            int s = tid >> 3, dg = (tid & 7)*4;
            float o[4] = {0.f, 0.f, 0.f, 0.f};
#pragma unroll
            for (int w = 0; w < 8; w++)
#pragma unroll
                for (int j = 0; j < 4; j++) o[j] += Ob[w*1056 + s*33 + dg + j];
            size_t base = ((size_t)bh*NS + s0 + s)*NDH + dh*32 + dg;
            *(uint32_t*)(g_HOh + base)     = pack_h(o[0], o[1]);
            *(uint32_t*)(g_HOh + base + 2) = pack_h(o[2], o[3]);
        }
        __syncthreads();
    }
}

// ---------------------------------------------------------------------------
// k_out_mma: 128x128 tile, pure fp16, 16 chunks double-buffered, occ 2.
// Stage (words): Ah@0 (4608) | Bh@4608 (4608) -> 9216 w = 36864 B; total 73728
// ---------------------------------------------------------------------------
__global__ void __launch_bounds__(256, 2) k_out_mma(const float* __restrict__ Ob,
                                                    float* __restrict__ out)
{
    extern __shared__ uint32_t sm32[];
    int tid = threadIdx.x, wid = tid >> 5, lane = tid & 31;
    int g = lane >> 2, t4 = lane & 3;
    int m0w = (wid & 3)*32, n0w = (wid >> 2)*64;
    int n0 = blockIdx.x << 7;
    int m0 = blockIdx.y << 7;
    int b  = blockIdx.y >> 2;
    int sbase = (blockIdx.y & 3) << 7;

    uint32_t sb = smem_u32(sm32);
    uint32_t lrow = lane & 15, lsel = (lane >> 4) << 4;

    float acc[2][8][4];
#pragma unroll
    for (int mi = 0; mi < 2; mi++)
#pragma unroll
        for (int nj = 0; nj < 8; nj++)
#pragma unroll
            for (int q = 0; q < 4; q++) acc[mi][nj][q] = 0.f;

    const uint4* gB4h = (const uint4*)(g_Owh + (size_t)n0*NDM);

#define LOAD_CHUNK_OUT(st, kc)                                                    \
    { uint32_t dst = sb + (st)*36864;                                             \
      const uint4* gA4h = (const uint4*)(g_HOh + ((size_t)(b*NH + (kc))*NS + sbase)*NDH); \
      for (int i = tid; i < 1024; i += 256) {                                     \
          int r = i >> 3, c = i & 7;                                              \
          cp16(dst + (r*36 + c*4)*4, gA4h + (size_t)r*8 + c);                     \
      }                                                                           \
      for (int i = tid; i < 1024; i += 256) {                                     \
          int r = i >> 3, c = i & 7;                                              \
          cp16(dst + (4608 + r*36 + c*4)*4, gB4h + (size_t)r*128 + (kc)*8 + c);   \
      } }

    LOAD_CHUNK_OUT(0, 0);
    cp_commit();
    for (int kc = 0; kc < 16; kc++) {
        if (kc < 15) {
            LOAD_CHUNK_OUT((kc+1)&1, kc+1);
            cp_commit();
            cp_waitg1();
        } else cp_waitg0();
        __syncthreads();
        uint32_t bu = sb + (kc&1)*36864;
        uint32_t aH  = bu + (m0w + lrow)*A_STRIDE_B + lsel;
        uint32_t bHo = bu + 18432 + (n0w + lrow)*A_STRIDE_B + lsel;
#pragma unroll
        for (int ks = 0; ks < 4; ks++) {
            uint32_t ah[2][4];
#pragma unroll
            for (int mi = 0; mi < 2; mi++)
                ldmx4(ah[mi][0],ah[mi][1],ah[mi][2],ah[mi][3], aH + mi*MI_STEP_B + ks*KS_STEP_B);
#pragma unroll
            for (int nj2 = 0; nj2 < 4; nj2++) {
                uint32_t bh[4];
                ldmx4(bh[0],bh[1],bh[2],bh[3], bHo + nj2*MI_STEP_B + ks*KS_STEP_B);
#pragma unroll
                for (int jj = 0; jj < 2; jj++) {
                    int nj = nj2*2 + jj;
#pragma unroll
                    for (int mi = 0; mi < 2; mi++)
                        mma16816(acc[mi][nj], ah[mi][0],ah[mi][1],ah[mi][2],ah[mi][3], bh[jj], bh[jj+2]);
                }
            }
        }
        __syncthreads();
    }

    float* Sg = (float*)sm32;   // [128][129]
#pragma unroll
    for (int mi = 0; mi < 2; mi++) {
        int m = m0w + mi*16 + g;
#pragma unroll
        for (int nj = 0; nj < 8; nj++) {
            int n = n0w + nj*8 + t4*2;
            float o0 = Ob[n0 + n];
            float o1 = Ob[n0 + n + 1];
            Sg[m*129 + n]         = acc[mi][nj][0] + o0;
            Sg[m*129 + n + 1]     = acc[mi][nj][1] + o1;
            Sg[(m+8)*129 + n]     = acc[mi][nj][2] + o0;
            Sg[(m+8)*129 + n + 1] = acc[mi][nj][3] + o1;
        }
    }
    __syncthreads();
    for (int i = tid; i < 4096; i += 256) {
        int r = i >> 5, c4 = (i & 31)*4;
        float4 v = make_float4(Sg[r*129 + c4], Sg[r*129 + c4 + 1],
                               Sg[r*129 + c4 + 2], Sg[r*129 + c4 + 3]);
        __stcs((float4*)(out + (size_t)(m0 + r)*NDM + n0 + c4), v);
    }
}

// ---------------------------------------------------------------------------
extern "C" void kernel_launch(void* const* d_in, const int* in_sizes, int n_in,
                              void* d_out, int out_size)
{
    const float* query = (const float*)d_in[0];
    const float* key   = (const float*)d_in[1];
    const float* value = (const float*)d_in[2];
    const float* Wq    = (const float*)d_in[3];
    const float* bq    = (const float*)d_in[4];
    const float* Wk    = (const float*)d_in[5];
    const float* bk    = (const float*)d_in[6];
    const float* Wv    = (const float*)d_in[7];
    const float* bv    = (const float*)d_in[8];
    const float* E_w   = (const float*)d_in[9];
    const float* E_b   = (const float*)d_in[10];
    const float* F_w   = (const float*)d_in[11];
    const float* F_b   = (const float*)d_in[12];
    const float* out_w = (const float*)d_in[13];
    const float* out_b = (const float*)d_in[14];

    const long long mha_elems  = (long long)NB*NS*NDM;
    const long long attn_elems = (long long)BH*NS*NT;

    float* outp = (float*)d_out;
    float* mha_ptr;
    float* attn_ptr;
    if ((long long)out_size >= mha_elems + attn_elems) {
        mha_ptr  = outp;
        attn_ptr = outp + mha_elems;
    } else if ((long long)out_size == attn_elems) {
        attn_ptr = outp;
        cudaGetSymbolAddress((void**)&mha_ptr, g_MHA_FB);
    } else {
        mha_ptr = outp;
        cudaGetSymbolAddress((void**)&attn_ptr, g_ATTN_FB);
    }

    cudaFuncSetAttribute(k_qkv_mma,    cudaFuncAttributeMaxDynamicSharedMemorySize, 36864);
    cudaFuncSetAttribute(k_kevf_mma,   cudaFuncAttributeMaxDynamicSharedMemorySize, 55296);
    cudaFuncSetAttribute(k_out_mma,    cudaFuncAttributeMaxDynamicSharedMemorySize, 73728);
    cudaFuncSetAttribute(k_attn_fused, cudaFuncAttributeMaxDynamicSharedMemorySize, 43520);

    k_split6<<<((3*NX + 3*NW)/4 + 255)/256, 256>>>(query, key, value, Wq, Wk, Wv);
    k_split3<<<((2*NT*NS + NDM*NDM)/4 + 255)/256, 256>>>(E_w, F_w, out_w);
    k_qkv_mma<<<dim3(BH, 4, 3), 256, 36864>>>(bq, bk, bv);
    k_kevf_mma<<<dim3(BH, 4, 2), 256, 55296>>>(E_b, F_b);
    k_attn_fused<<<dim3(16, BH), 256, 43520>>>(attn_ptr);
    k_out_mma<<<dim3(NDM/128, (NB*NS)/128), 256, 73728>>>(out_b, mha_ptr);
}